// round 11
// baseline (speedup 1.0000x reference)
#include <cuda_runtime.h>
#include <cstdint>

#define DM 2048
static __device__ float g_q [128*2048];
static __device__ float g_kn[128*2048];
static __device__ float g_vn[128*2048];
static __device__ float g_ao[128*2048];
static __device__ float g_part[4*128*2048];

__device__ __forceinline__ uint32_t f2t(float x){
    uint32_t r; asm("cvt.rna.tf32.f32 %0,%1;":"=r"(r):"f"(x)); return r;
}
__device__ __forceinline__ float tf(float x){ return __uint_as_float(f2t(x)); }
__device__ __forceinline__ float ex2(float x){
    float r; asm("ex2.approx.ftz.f32 %0,%1;":"=f"(r):"f"(x)); return r;
}
__device__ __forceinline__ void mma8(float* c,uint32_t a0,uint32_t a1,uint32_t a2,uint32_t a3,
                                     uint32_t b0,uint32_t b1){
    asm volatile("mma.sync.aligned.m16n8k8.row.col.f32.tf32.tf32.f32 "
        "{%0,%1,%2,%3},{%4,%5,%6,%7},{%8,%9},{%0,%1,%2,%3};"
        :"+f"(c[0]),"+f"(c[1]),"+f"(c[2]),"+f"(c[3])
        :"r"(a0),"r"(a1),"r"(a2),"r"(a3),"r"(b0),"r"(b1));
}
__device__ __forceinline__ void cpa16(float* s, const float* g){
    uint32_t sa=(uint32_t)__cvta_generic_to_shared(s);
    asm volatile("cp.async.cg.shared.global [%0],[%1],16;" :: "r"(sa),"l"(g));
}
__device__ __forceinline__ void cpcommit(){ asm volatile("cp.async.commit_group;"); }
__device__ __forceinline__ void cpwait0(){ asm volatile("cp.async.wait_group 0;"); }
__device__ __forceinline__ void cpwait1(){ asm volatile("cp.async.wait_group 1;"); }
__device__ __forceinline__ void cpwait2(){ asm volatile("cp.async.wait_group 2;"); }

// ======================= GEMM (unchanged) =================================
#define GEMM_SMEM ((2*128*36 + 2*32*72)*4)

template<int MODE>
__global__ __launch_bounds__(512) void gemm_k(const float* __restrict__ A,
    const float* __restrict__ W0,const float* __restrict__ W1,const float* __restrict__ W2,
    const float* __restrict__ B0,const float* __restrict__ B1,const float* __restrict__ B2)
{
    extern __shared__ float sm[];
    float* Xs = sm;
    float* Ws = sm + 2*4608;
    int tid=threadIdx.x, lane=tid&31, warp=tid>>5, tg=lane&3, gid=lane>>2;
    int sel = MODE? 0 : blockIdx.y;
    const float* W  = sel==0?W0: sel==1?W1:W2;
    const float* Bi = sel==0?B0: sel==1?B1:B2;
    const float* Ap = MODE? g_ao : A;
    int n0 = blockIdx.x*64;
    int kcb = MODE? blockIdx.y*16 : 0;
    int kcn = MODE? 16 : 64;
    int m0 = (warp&7)*16, nb = (warp>>3)*32;
    float acc[4][4];
    #pragma unroll
    for(int i=0;i<4;i++){acc[i][0]=acc[i][1]=acc[i][2]=acc[i][3]=0.f;}

    auto issue=[&](int b,int kc){
        #pragma unroll
        for(int j=0;j<2;j++){ int id=tid+j*512; int r=id>>3, c4=(id&7)<<2;
            cpa16(&Xs[b*4608 + r*36 + c4], &Ap[r*DM + kc*32 + c4]); }
        { int r=tid>>4, c4=(tid&15)<<2;
            cpa16(&Ws[b*2304 + r*72 + c4], &W[(kc*32+r)*DM + n0 + c4]); }
        cpcommit();
    };
    issue(0,kcb);
    for(int i=0;i<kcn;i++){
        if(i<kcn-1){ issue((i+1)&1, kcb+i+1); cpwait1(); } else cpwait0();
        __syncthreads();
        const float* xb = &Xs[(i&1)*4608];
        const float* wb = &Ws[(i&1)*2304];
        #pragma unroll
        for(int kk=0;kk<32;kk+=8){
            uint32_t a0=f2t(xb[(m0+gid)*36+kk+tg]);
            uint32_t a1=f2t(xb[(m0+gid+8)*36+kk+tg]);
            uint32_t a2=f2t(xb[(m0+gid)*36+kk+tg+4]);
            uint32_t a3=f2t(xb[(m0+gid+8)*36+kk+tg+4]);
            #pragma unroll
            for(int nt=0;nt<4;nt++){
                uint32_t b0=f2t(wb[(kk+tg)*72+nb+nt*8+gid]);
                uint32_t b1=f2t(wb[(kk+tg+4)*72+nb+nt*8+gid]);
                mma8(acc[nt],a0,a1,a2,a3,b0,b1);
            }
        }
        __syncthreads();
    }
    #pragma unroll
    for(int nt=0;nt<4;nt++){
        #pragma unroll
        for(int c=0;c<4;c++){
            int row=m0+gid+((c>>1)<<3);
            int col=n0+nb+nt*8+2*tg+(c&1);
            if(MODE){
                g_part[blockIdx.y*262144 + row*DM + col] = acc[nt][c];
            }else{
                float v=acc[nt][c]+Bi[col];
                float* dst = sel==0?g_q: sel==1?g_kn:g_vn;
                dst[(((row>>4)<<4)|(col>>7))*2048 + (row&15)*128 + (col&127)] = v;
            }
        }
    }
}

__global__ __launch_bounds__(512) void reduce_k(const float* __restrict__ Bo,
                                                float* __restrict__ O)
{
    int idx = blockIdx.x*512 + threadIdx.x;
    int base = idx*4, col = base & 2047;
    float4 p0=*(const float4*)&g_part[base];
    float4 p1=*(const float4*)&g_part[262144+base];
    float4 p2=*(const float4*)&g_part[524288+base];
    float4 p3=*(const float4*)&g_part[786432+base];
    float4 b=*(const float4*)&Bo[col];
    float4 o;
    o.x=p0.x+p1.x+p2.x+p3.x+b.x; o.y=p0.y+p1.y+p2.y+p3.y+b.y;
    o.z=p0.z+p1.z+p2.z+p3.z+b.z; o.w=p0.w+p1.w+p2.w+p3.w+b.w;
    *(float4*)&O[base]=o;
}

// ======================= Flash attention (warp-specialized) ===============
// 512 threads. Warps 0-7: QK + softmax for keys [8w,8w+8) of each 64-key
// tile; publish P(t) + PER-ROW rescale factors. Warps 8-15: PV of tile t-1.
// K/V in 3-buffer cp.async rings. Merge at the end.
#define KSTR 132
#define VSTR 136
#define KB 8448
#define VB 8704
#define ATTN_SMEM ((3*KB + 3*VB + 2112 + 2*8*192 + 2*8*16)*4)

__global__ __launch_bounds__(512) void attn_k(const float* __restrict__ kc_,
                                              const float* __restrict__ vc_)
{
    extern __shared__ float sm[];
    float* Ks  = sm;                 // [3][64*132]
    float* Vs  = sm + 3*KB;          // [3][64*136]
    float* qs  = Vs + 3*VB;          // [16*132]
    float* psm = qs + 2112;          // [2][8][16*12]
    float* fsh = psm + 2*1536;       // [2][8][16]  per-row rescale factors
    // merge scratch aliased onto Ks (dead after main loop):
    float* Osum = sm;                // [16*132]
    float* Lsum = sm + 2112;         // [16]
    float* msh  = sm + 2128;         // [8][16]
    int tid=threadIdx.x, lane=tid&31, warp=tid>>5, tg=lane&3, gid=lane>>2;
    int bh=blockIdx.x;
    const float cs = 0.08838834764831843f * 1.4426950408889634f;
    {
        float4 v=*(const float4*)&g_q[bh*2048+tid*4];
        int r=tid>>5, c4=(tid&31)<<2;
        qs[r*132+c4+0]=tf(v.x*cs); qs[r*132+c4+1]=tf(v.y*cs);
        qs[r*132+c4+2]=tf(v.z*cs); qs[r*132+c4+3]=tf(v.w*cs);
    }
    const float* Kc = kc_ + (size_t)bh*4096*128;
    const float* Vc = vc_ + (size_t)bh*4096*128;

    auto issueK=[&](int b,int t){
        #pragma unroll
        for(int j=0;j<4;j++){ int id=tid+j*512; int r=id>>5, c4=(id&31)<<2;
            cpa16(&Ks[b*KB + r*KSTR + c4], &Kc[(size_t)(t*64+r)*128 + c4]); }
        cpcommit();
    };
    auto issueV=[&](int b,int t){
        #pragma unroll
        for(int j=0;j<4;j++){ int id=tid+j*512; int r=id>>5, c4=(id&31)<<2;
            cpa16(&Vs[b*VB + r*VSTR + c4], &Vc[(size_t)(t*64+r)*128 + c4]); }
        cpcommit();
    };
    issueK(0,0); issueV(0,0); issueK(1,1);
    __syncthreads();   // qs ready

    float m0=-1e30f,m1=-1e30f,l0=0.f,l1=0.f;   // QK warps (per-lane rows gid/gid+8)
    float accO[16][4];                          // PV warps
    #pragma unroll
    for(int i=0;i<16;i++){accO[i][0]=accO[i][1]=accO[i][2]=accO[i][3]=0.f;}

    for(int t=0;t<64;t++){
        if(t<63) cpwait2(); else cpwait1();
        __syncthreads();
        if(t<63) issueV((t+1)%3, t+1);
        if(t<62) issueK((t+2)%3, t+2);
        if(warp<8){
            const float* Kb=&Ks[(t%3)*KB];
            float s[4]={0.f,0.f,0.f,0.f};
            #pragma unroll
            for(int k8=0;k8<16;k8++){
                uint32_t a0=__float_as_uint(qs[gid*132+k8*8+tg]);
                uint32_t a1=__float_as_uint(qs[(gid+8)*132+k8*8+tg]);
                uint32_t a2=__float_as_uint(qs[gid*132+k8*8+tg+4]);
                uint32_t a3=__float_as_uint(qs[(gid+8)*132+k8*8+tg+4]);
                uint32_t b0=f2t(Kb[(warp*8+gid)*KSTR+k8*8+tg]);
                uint32_t b1=f2t(Kb[(warp*8+gid)*KSTR+k8*8+tg+4]);
                mma8(s,a0,a1,a2,a3,b0,b1);
            }
            float x0=fmaxf(s[0],s[1]), x1=fmaxf(s[2],s[3]);
            x0=fmaxf(x0,__shfl_xor_sync(~0u,x0,1)); x0=fmaxf(x0,__shfl_xor_sync(~0u,x0,2));
            x1=fmaxf(x1,__shfl_xor_sync(~0u,x1,1)); x1=fmaxf(x1,__shfl_xor_sync(~0u,x1,2));
            float nm0=fmaxf(m0,x0), nm1=fmaxf(m1,x1);
            float f0=ex2(m0-nm0), f1=ex2(m1-nm1);
            m0=nm0; m1=nm1;
            float p0=ex2(s[0]-nm0), p1=ex2(s[1]-nm0);
            float p2=ex2(s[2]-nm1), p3=ex2(s[3]-nm1);
            float su0=p0+p1, su1=p2+p3;
            su0+=__shfl_xor_sync(~0u,su0,1); su0+=__shfl_xor_sync(~0u,su0,2);
            su1+=__shfl_xor_sync(~0u,su1,1); su1+=__shfl_xor_sync(~0u,su1,2);
            l0=l0*f0+su0; l1=l1*f1+su1;
            float* pw = psm + (t&1)*1536 + warp*192;
            pw[gid*12+2*tg]=p0;     pw[gid*12+2*tg+1]=p1;
            pw[(gid+8)*12+2*tg]=p2; pw[(gid+8)*12+2*tg+1]=p3;
            if(tg==0){ float* fp=fsh+(t&1)*128+warp*16; fp[gid]=f0; fp[gid+8]=f1; }
        } else if(t>0){
            int w=warp-8;
            const float* Vb=&Vs[((t-1)%3)*VB];
            const float* pp=psm + ((t-1)&1)*1536 + w*192;
            const float* fp=fsh + ((t-1)&1)*128 + w*16;
            float ff0=fp[gid], ff1=fp[gid+8];               // per-row factors
            #pragma unroll
            for(int i=0;i<16;i++){accO[i][0]*=ff0;accO[i][1]*=ff0;accO[i][2]*=ff1;accO[i][3]*=ff1;}
            uint32_t h0=f2t(pp[gid*12+tg]);
            uint32_t h1=f2t(pp[(gid+8)*12+tg]);
            uint32_t h2=f2t(pp[gid*12+tg+4]);
            uint32_t h3=f2t(pp[(gid+8)*12+tg+4]);
            #pragma unroll
            for(int nt=0;nt<16;nt++){
                uint32_t b0=f2t(Vb[(w*8+tg)*VSTR+nt*8+gid]);
                uint32_t b1=f2t(Vb[(w*8+tg+4)*VSTR+nt*8+gid]);
                mma8(accO[nt],h0,h1,h2,h3,b0,b1);
            }
        }
    }
    cpwait0();
    __syncthreads();

    // phase A: QK warps 0-1 process the 16 new keys; PV warps do PV(63)
    if(warp<2){
        const float* Kp = g_kn + bh*2048 + warp*8*128;
        float s[4]={0.f,0.f,0.f,0.f};
        #pragma unroll
        for(int k8=0;k8<16;k8++){
            uint32_t a0=__float_as_uint(qs[gid*132+k8*8+tg]);
            uint32_t a1=__float_as_uint(qs[(gid+8)*132+k8*8+tg]);
            uint32_t a2=__float_as_uint(qs[gid*132+k8*8+tg+4]);
            uint32_t a3=__float_as_uint(qs[(gid+8)*132+k8*8+tg+4]);
            uint32_t b0=f2t(Kp[gid*128+k8*8+tg]);
            uint32_t b1=f2t(Kp[gid*128+k8*8+tg+4]);
            mma8(s,a0,a1,a2,a3,b0,b1);
        }
        #pragma unroll
        for(int c=0;c<4;c++){
            int col16=warp*8+2*tg+(c&1), row=gid+((c>>1)<<3);
            if(col16>row) s[c]=-1e30f;
        }
        float x0=fmaxf(s[0],s[1]), x1=fmaxf(s[2],s[3]);
        x0=fmaxf(x0,__shfl_xor_sync(~0u,x0,1)); x0=fmaxf(x0,__shfl_xor_sync(~0u,x0,2));
        x1=fmaxf(x1,__shfl_xor_sync(~0u,x1,1)); x1=fmaxf(x1,__shfl_xor_sync(~0u,x1,2));
        float nm0=fmaxf(m0,x0), nm1=fmaxf(m1,x1);
        float f0=ex2(m0-nm0), f1=ex2(m1-nm1);
        m0=nm0; m1=nm1;
        float p0=ex2(s[0]-nm0), p1=ex2(s[1]-nm0);
        float p2=ex2(s[2]-nm1), p3=ex2(s[3]-nm1);
        float su0=p0+p1, su1=p2+p3;
        su0+=__shfl_xor_sync(~0u,su0,1); su0+=__shfl_xor_sync(~0u,su0,2);
        su1+=__shfl_xor_sync(~0u,su1,1); su1+=__shfl_xor_sync(~0u,su1,2);
        l0=l0*f0+su0; l1=l1*f1+su1;
        float* pw = psm + 0*1536 + warp*192;    // parity of "tile 64" = 0
        pw[gid*12+2*tg]=p0;     pw[gid*12+2*tg+1]=p1;
        pw[(gid+8)*12+2*tg]=p2; pw[(gid+8)*12+2*tg+1]=p3;
        if(tg==0){ float* fp=fsh+warp*16; fp[gid]=f0; fp[gid+8]=f1; }
    } else if(warp>=8){
        int w=warp-8;
        const float* Vb=&Vs[(63%3)*VB];
        const float* pp=psm + (63&1)*1536 + w*192;
        const float* fp=fsh + (63&1)*128 + w*16;
        float ff0=fp[gid], ff1=fp[gid+8];
        #pragma unroll
        for(int i=0;i<16;i++){accO[i][0]*=ff0;accO[i][1]*=ff0;accO[i][2]*=ff1;accO[i][3]*=ff1;}
        uint32_t h0=f2t(pp[gid*12+tg]);
        uint32_t h1=f2t(pp[(gid+8)*12+tg]);
        uint32_t h2=f2t(pp[gid*12+tg+4]);
        uint32_t h3=f2t(pp[(gid+8)*12+tg+4]);
        #pragma unroll
        for(int nt=0;nt<16;nt++){
            uint32_t b0=f2t(Vb[(w*8+tg)*VSTR+nt*8+gid]);
            uint32_t b1=f2t(Vb[(w*8+tg+4)*VSTR+nt*8+gid]);
            mma8(accO[nt],h0,h1,h2,h3,b0,b1);
        }
    }
    __syncthreads();

    // phase B: PV warps 8-9 fold in the new keys
    if(warp>=8 && warp<10){
        int w=warp-8;
        const float* Vp = g_vn + bh*2048 + w*8*128;
        const float* pp=psm + w*192;
        const float* fp=fsh + w*16;
        float ff0=fp[gid], ff1=fp[gid+8];
        #pragma unroll
        for(int i=0;i<16;i++){accO[i][0]*=ff0;accO[i][1]*=ff0;accO[i][2]*=ff1;accO[i][3]*=ff1;}
        uint32_t h0=f2t(pp[gid*12+tg]);
        uint32_t h1=f2t(pp[(gid+8)*12+tg]);
        uint32_t h2=f2t(pp[gid*12+tg+4]);
        uint32_t h3=f2t(pp[(gid+8)*12+tg+4]);
        #pragma unroll
        for(int nt=0;nt<16;nt++){
            uint32_t b0=f2t(Vp[tg*128+nt*8+gid]);
            uint32_t b1=f2t(Vp[(tg+4)*128+nt*8+gid]);
            mma8(accO[nt],h0,h1,h2,h3,b0,b1);
        }
    }
    __syncthreads();

    // merge: zero scratch (aliased on Ks), publish per-lineage maxima
    for(int j=tid;j<2128;j+=512) sm[j]=0.f;
    if(warp<8 && tg==0){ msh[warp*16+gid]=m0; msh[warp*16+gid+8]=m1; }
    __syncthreads();
    float M0=-1e30f,M1=-1e30f;
    #pragma unroll
    for(int w=0;w<8;w++){ M0=fmaxf(M0,msh[w*16+gid]); M1=fmaxf(M1,msh[w*16+gid+8]); }
    if(warp<8){
        if(tg==0){
            float sc0=ex2(m0-M0), sc1=ex2(m1-M1);
            atomicAdd(&Lsum[gid],l0*sc0); atomicAdd(&Lsum[gid+8],l1*sc1);
        }
    } else {
        int w=warp-8;
        float sc0=ex2(msh[w*16+gid]-M0), sc1=ex2(msh[w*16+gid+8]-M1);
        #pragma unroll
        for(int nt=0;nt<16;nt++){
            atomicAdd(&Osum[gid*132+nt*8+2*tg],       accO[nt][0]*sc0);
            atomicAdd(&Osum[gid*132+nt*8+2*tg+1],     accO[nt][1]*sc0);
            atomicAdd(&Osum[(gid+8)*132+nt*8+2*tg],   accO[nt][2]*sc1);
            atomicAdd(&Osum[(gid+8)*132+nt*8+2*tg+1], accO[nt][3]*sc1);
        }
    }
    __syncthreads();
    int b=bh>>4, h=bh&15;
    {
        int j=tid;
        #pragma unroll
        for(int r=0;r<4;r++){
            int e=j*4+r, s_=e>>7, d=e&127;
            g_ao[(b*16+s_)*2048 + h*128 + d] = Osum[s_*132+d]/Lsum[s_];
        }
    }
}

extern "C" void kernel_launch(void* const* d_in, const int* in_sizes, int n_in,
                              void* d_out, int out_size)
{
    const float* x =(const float*)d_in[0];
    const float* kc=(const float*)d_in[1];
    const float* vc=(const float*)d_in[2];
    const float* Wq=(const float*)d_in[3]; const float* bq=(const float*)d_in[4];
    const float* Wk=(const float*)d_in[5]; const float* bk=(const float*)d_in[6];
    const float* Wv=(const float*)d_in[7]; const float* bv=(const float*)d_in[8];
    const float* Wo=(const float*)d_in[9]; const float* bo=(const float*)d_in[10];
    cudaFuncSetAttribute(gemm_k<0>, cudaFuncAttributeMaxDynamicSharedMemorySize, GEMM_SMEM);
    cudaFuncSetAttribute(gemm_k<1>, cudaFuncAttributeMaxDynamicSharedMemorySize, GEMM_SMEM);
    cudaFuncSetAttribute(attn_k,    cudaFuncAttributeMaxDynamicSharedMemorySize, ATTN_SMEM);
    gemm_k<0><<<dim3(32,3),512,GEMM_SMEM>>>(x,Wq,Wk,Wv,bq,bk,bv);
    attn_k<<<128,512,ATTN_SMEM>>>(kc,vc);
    gemm_k<1><<<dim3(32,4),512,GEMM_SMEM>>>(nullptr,Wo,Wo,Wo,bo,bo,bo);
    reduce_k<<<128,512>>>(bo,(float*)d_out);
}

// round 12
// speedup vs baseline: 1.0141x; 1.0141x over previous
#include <cuda_runtime.h>
#include <cstdint>

#define DM 2048
static __device__ float g_q [128*2048];
static __device__ float g_kn[128*2048];
static __device__ float g_vn[128*2048];
static __device__ float g_ao[128*2048];
static __device__ float g_part[4*128*2048];

__device__ __forceinline__ uint32_t f2t(float x){
    uint32_t r; asm("cvt.rna.tf32.f32 %0,%1;":"=r"(r):"f"(x)); return r;
}
__device__ __forceinline__ float tf(float x){ return __uint_as_float(f2t(x)); }
__device__ __forceinline__ float ex2(float x){
    float r; asm("ex2.approx.ftz.f32 %0,%1;":"=f"(r):"f"(x)); return r;
}
__device__ __forceinline__ void mma8(float* c,uint32_t a0,uint32_t a1,uint32_t a2,uint32_t a3,
                                     uint32_t b0,uint32_t b1){
    asm volatile("mma.sync.aligned.m16n8k8.row.col.f32.tf32.tf32.f32 "
        "{%0,%1,%2,%3},{%4,%5,%6,%7},{%8,%9},{%0,%1,%2,%3};"
        :"+f"(c[0]),"+f"(c[1]),"+f"(c[2]),"+f"(c[3])
        :"r"(a0),"r"(a1),"r"(a2),"r"(a3),"r"(b0),"r"(b1));
}
__device__ __forceinline__ void cpa16(float* s, const float* g){
    uint32_t sa=(uint32_t)__cvta_generic_to_shared(s);
    asm volatile("cp.async.cg.shared.global [%0],[%1],16;" :: "r"(sa),"l"(g));
}
__device__ __forceinline__ void cpcommit(){ asm volatile("cp.async.commit_group;"); }
__device__ __forceinline__ void cpwait0(){ asm volatile("cp.async.wait_group 0;"); }
__device__ __forceinline__ void cpwait1(){ asm volatile("cp.async.wait_group 1;"); }

// ======================= GEMM (round-9, known good) =======================
#define GEMM_SMEM ((2*128*36 + 2*32*72)*4)

template<int MODE>
__global__ __launch_bounds__(512) void gemm_k(const float* __restrict__ A,
    const float* __restrict__ W0,const float* __restrict__ W1,const float* __restrict__ W2,
    const float* __restrict__ B0,const float* __restrict__ B1,const float* __restrict__ B2)
{
    extern __shared__ float sm[];
    float* Xs = sm;
    float* Ws = sm + 2*4608;
    int tid=threadIdx.x, lane=tid&31, warp=tid>>5, tg=lane&3, gid=lane>>2;
    int sel = MODE? 0 : blockIdx.y;
    const float* W  = sel==0?W0: sel==1?W1:W2;
    const float* Bi = sel==0?B0: sel==1?B1:B2;
    const float* Ap = MODE? g_ao : A;
    int n0 = blockIdx.x*64;
    int kcb = MODE? blockIdx.y*16 : 0;
    int kcn = MODE? 16 : 64;
    int m0 = (warp&7)*16, nb = (warp>>3)*32;
    float acc[4][4];
    #pragma unroll
    for(int i=0;i<4;i++){acc[i][0]=acc[i][1]=acc[i][2]=acc[i][3]=0.f;}

    auto issue=[&](int b,int kc){
        #pragma unroll
        for(int j=0;j<2;j++){ int id=tid+j*512; int r=id>>3, c4=(id&7)<<2;
            cpa16(&Xs[b*4608 + r*36 + c4], &Ap[r*DM + kc*32 + c4]); }
        { int r=tid>>4, c4=(tid&15)<<2;
            cpa16(&Ws[b*2304 + r*72 + c4], &W[(kc*32+r)*DM + n0 + c4]); }
        cpcommit();
    };
    issue(0,kcb);
    for(int i=0;i<kcn;i++){
        if(i<kcn-1){ issue((i+1)&1, kcb+i+1); cpwait1(); } else cpwait0();
        __syncthreads();
        const float* xb = &Xs[(i&1)*4608];
        const float* wb = &Ws[(i&1)*2304];
        #pragma unroll
        for(int kk=0;kk<32;kk+=8){
            uint32_t a0=f2t(xb[(m0+gid)*36+kk+tg]);
            uint32_t a1=f2t(xb[(m0+gid+8)*36+kk+tg]);
            uint32_t a2=f2t(xb[(m0+gid)*36+kk+tg+4]);
            uint32_t a3=f2t(xb[(m0+gid+8)*36+kk+tg+4]);
            #pragma unroll
            for(int nt=0;nt<4;nt++){
                uint32_t b0=f2t(wb[(kk+tg)*72+nb+nt*8+gid]);
                uint32_t b1=f2t(wb[(kk+tg+4)*72+nb+nt*8+gid]);
                mma8(acc[nt],a0,a1,a2,a3,b0,b1);
            }
        }
        __syncthreads();
    }
    #pragma unroll
    for(int nt=0;nt<4;nt++){
        #pragma unroll
        for(int c=0;c<4;c++){
            int row=m0+gid+((c>>1)<<3);
            int col=n0+nb+nt*8+2*tg+(c&1);
            if(MODE){
                g_part[blockIdx.y*262144 + row*DM + col] = acc[nt][c];
            }else{
                float v=acc[nt][c]+Bi[col];
                float* dst = sel==0?g_q: sel==1?g_kn:g_vn;
                dst[(((row>>4)<<4)|(col>>7))*2048 + (row&15)*128 + (col&127)] = v;
            }
        }
    }
}

__global__ __launch_bounds__(512) void reduce_k(const float* __restrict__ Bo,
                                                float* __restrict__ O)
{
    int idx = blockIdx.x*512 + threadIdx.x;
    int base = idx*4, col = base & 2047;
    float4 p0=*(const float4*)&g_part[base];
    float4 p1=*(const float4*)&g_part[262144+base];
    float4 p2=*(const float4*)&g_part[524288+base];
    float4 p3=*(const float4*)&g_part[786432+base];
    float4 b=*(const float4*)&Bo[col];
    float4 o;
    o.x=p0.x+p1.x+p2.x+p3.x+b.x; o.y=p0.y+p1.y+p2.y+p3.y+b.y;
    o.z=p0.z+p1.z+p2.z+p3.z+b.z; o.w=p0.w+p1.w+p2.w+p3.w+b.w;
    *(float4*)&O[base]=o;
}

// ======================= Flash attention (round-9 + chain/barrier fixes) ==
// 1 CTA per (b,h), 8 warps; warp w owns keys [8w,8w+8) of each 64-key tile,
// private online softmax + 16x128 accO. K ring depth 3, V ring depth 2,
// ONE __syncthreads per tile. Dual QK accumulators halve the mma RAW chain.
#define KSTR 132
#define VSTR 136
#define KB 8448
#define VB 8704
#define ATTN_SMEM ((3*KB + 2*VB + 2112 + 8*192)*4)

__global__ __launch_bounds__(256) void attn_k(const float* __restrict__ kc_,
                                              const float* __restrict__ vc_)
{
    extern __shared__ float sm[];
    float* Ks   = sm;                 // [3][64*132]
    float* Vs   = sm + 3*KB;          // [2][64*136]
    float* qs   = Vs + 2*VB;          // [16*132]
    float* psm  = qs + 2112;          // [8][16*12]
    // merge scratch aliased onto Ks (dead after main loop):
    float* Osum = sm;                 // [16*132]
    float* Lsum = sm + 2112;          // [16]
    float* msh  = sm + 2128;          // [8][16]
    int tid=threadIdx.x, lane=tid&31, warp=tid>>5, tg=lane&3, gid=lane>>2;
    int bh=blockIdx.x;
    const float cs = 0.08838834764831843f * 1.4426950408889634f;
    #pragma unroll
    for(int j=tid;j<512;j+=256){
        float4 v=*(const float4*)&g_q[bh*2048+j*4];
        int r=j>>5, c4=(j&31)<<2;
        qs[r*132+c4+0]=tf(v.x*cs); qs[r*132+c4+1]=tf(v.y*cs);
        qs[r*132+c4+2]=tf(v.z*cs); qs[r*132+c4+3]=tf(v.w*cs);
    }
    const float* Kc = kc_ + (size_t)bh*4096*128;
    const float* Vc = vc_ + (size_t)bh*4096*128;

    auto issueK=[&](int t){
        float* dst=&Ks[(t%3)*KB];
        #pragma unroll
        for(int j=0;j<8;j++){ int id=tid+j*256; int r=id>>5, c4=(id&31)<<2;
            cpa16(&dst[r*KSTR + c4], &Kc[(size_t)(t*64+r)*128 + c4]); }
    };
    auto issueV=[&](int t){
        float* dst=&Vs[(t&1)*VB];
        #pragma unroll
        for(int j=0;j<8;j++){ int id=tid+j*256; int r=id>>5, c4=(id&31)<<2;
            cpa16(&dst[r*VSTR + c4], &Vc[(size_t)(t*64+r)*128 + c4]); }
    };
    issueK(0); issueV(0); issueK(1); cpcommit();
    __syncthreads();   // qs ready

    // hoist Q fragments to registers (rounded+scaled)
    uint32_t aq0[16],aq1[16],aq2[16],aq3[16];
    #pragma unroll
    for(int k8=0;k8<16;k8++){
        aq0[k8]=__float_as_uint(qs[gid*132+k8*8+tg]);
        aq1[k8]=__float_as_uint(qs[(gid+8)*132+k8*8+tg]);
        aq2[k8]=__float_as_uint(qs[gid*132+k8*8+tg+4]);
        aq3[k8]=__float_as_uint(qs[(gid+8)*132+k8*8+tg+4]);
    }

    float accO[16][4];
    #pragma unroll
    for(int i=0;i<16;i++){accO[i][0]=accO[i][1]=accO[i][2]=accO[i][3]=0.f;}
    float m0=-1e30f,m1=-1e30f,l0=0.f,l1=0.f;
    float* pw = psm + warp*192;

    for(int t=0;t<64;t++){
        cpwait0();
        __syncthreads();             // single barrier per tile
        if(t+2<64) issueK(t+2);
        if(t+1<64) issueV(t+1);
        cpcommit();
        const float* Kb=&Ks[(t%3)*KB];
        const float* Vb=&Vs[(t&1)*VB];
        // QK with dual accumulators (halved RAW chain)
        float se[4]={0.f,0.f,0.f,0.f}, so[4]={0.f,0.f,0.f,0.f};
        #pragma unroll
        for(int k8=0;k8<16;k8+=2){
            uint32_t b0=f2t(Kb[(warp*8+gid)*KSTR+k8*8+tg]);
            uint32_t b1=f2t(Kb[(warp*8+gid)*KSTR+k8*8+tg+4]);
            mma8(se,aq0[k8],aq1[k8],aq2[k8],aq3[k8],b0,b1);
            uint32_t c0=f2t(Kb[(warp*8+gid)*KSTR+(k8+1)*8+tg]);
            uint32_t c1=f2t(Kb[(warp*8+gid)*KSTR+(k8+1)*8+tg+4]);
            mma8(so,aq0[k8+1],aq1[k8+1],aq2[k8+1],aq3[k8+1],c0,c1);
        }
        float s[4];
        #pragma unroll
        for(int c=0;c<4;c++) s[c]=se[c]+so[c];
        float x0=fmaxf(s[0],s[1]), x1=fmaxf(s[2],s[3]);
        x0=fmaxf(x0,__shfl_xor_sync(~0u,x0,1)); x0=fmaxf(x0,__shfl_xor_sync(~0u,x0,2));
        x1=fmaxf(x1,__shfl_xor_sync(~0u,x1,1)); x1=fmaxf(x1,__shfl_xor_sync(~0u,x1,2));
        bool upd = __any_sync(~0u,(x0>m0)||(x1>m1));
        float nm0=fmaxf(m0,x0), nm1=fmaxf(m1,x1);
        float f0=1.f,f1=1.f;
        if(upd){
            f0=ex2(m0-nm0); f1=ex2(m1-nm1);
            m0=nm0; m1=nm1;
            #pragma unroll
            for(int i=0;i<16;i++){accO[i][0]*=f0;accO[i][1]*=f0;accO[i][2]*=f1;accO[i][3]*=f1;}
        }
        float p0=ex2(s[0]-nm0), p1=ex2(s[1]-nm0);
        float p2=ex2(s[2]-nm1), p3=ex2(s[3]-nm1);
        float su0=p0+p1, su1=p2+p3;
        su0+=__shfl_xor_sync(~0u,su0,1); su0+=__shfl_xor_sync(~0u,su0,2);
        su1+=__shfl_xor_sync(~0u,su1,1); su1+=__shfl_xor_sync(~0u,su1,2);
        l0=l0*f0+su0; l1=l1*f1+su1;
        pw[gid*12+2*tg]=p0;     pw[gid*12+2*tg+1]=p1;
        pw[(gid+8)*12+2*tg]=p2; pw[(gid+8)*12+2*tg+1]=p3;
        __syncwarp();
        uint32_t h0=f2t(pw[gid*12+tg]);
        uint32_t h1=f2t(pw[(gid+8)*12+tg]);
        uint32_t h2=f2t(pw[gid*12+tg+4]);
        uint32_t h3=f2t(pw[(gid+8)*12+tg+4]);
        #pragma unroll
        for(int nt=0;nt<16;nt++){
            uint32_t b0=f2t(Vb[(warp*8+tg)*VSTR+nt*8+gid]);
            uint32_t b1=f2t(Vb[(warp*8+tg+4)*VSTR+nt*8+gid]);
            mma8(accO[nt],h0,h1,h2,h3,b0,b1);
        }
        __syncwarp();
    }
    __syncthreads();

    // tail: 16 new keys (warps 0-1, 8 keys each) with causal mask
    if(warp<2){
        const float* Kp = g_kn + bh*2048 + warp*8*128;
        const float* Vp = g_vn + bh*2048 + warp*8*128;
        float s[4]={0.f,0.f,0.f,0.f};
        #pragma unroll
        for(int k8=0;k8<16;k8++){
            uint32_t b0=f2t(Kp[gid*128+k8*8+tg]);
            uint32_t b1=f2t(Kp[gid*128+k8*8+tg+4]);
            mma8(s,aq0[k8],aq1[k8],aq2[k8],aq3[k8],b0,b1);
        }
        #pragma unroll
        for(int c=0;c<4;c++){
            int col16=warp*8+2*tg+(c&1), row=gid+((c>>1)<<3);
            if(col16>row) s[c]=-1e30f;
        }
        float x0=fmaxf(s[0],s[1]), x1=fmaxf(s[2],s[3]);
        x0=fmaxf(x0,__shfl_xor_sync(~0u,x0,1)); x0=fmaxf(x0,__shfl_xor_sync(~0u,x0,2));
        x1=fmaxf(x1,__shfl_xor_sync(~0u,x1,1)); x1=fmaxf(x1,__shfl_xor_sync(~0u,x1,2));
        float nm0=fmaxf(m0,x0), nm1=fmaxf(m1,x1);
        float f0=ex2(m0-nm0), f1=ex2(m1-nm1);
        m0=nm0; m1=nm1;
        float p0=ex2(s[0]-nm0), p1=ex2(s[1]-nm0);
        float p2=ex2(s[2]-nm1), p3=ex2(s[3]-nm1);
        float su0=p0+p1, su1=p2+p3;
        su0+=__shfl_xor_sync(~0u,su0,1); su0+=__shfl_xor_sync(~0u,su0,2);
        su1+=__shfl_xor_sync(~0u,su1,1); su1+=__shfl_xor_sync(~0u,su1,2);
        l0=l0*f0+su0; l1=l1*f1+su1;
        #pragma unroll
        for(int i=0;i<16;i++){accO[i][0]*=f0;accO[i][1]*=f0;accO[i][2]*=f1;accO[i][3]*=f1;}
        pw[gid*12+2*tg]=p0;     pw[gid*12+2*tg+1]=p1;
        pw[(gid+8)*12+2*tg]=p2; pw[(gid+8)*12+2*tg+1]=p3;
        __syncwarp();
        uint32_t h0=f2t(pw[gid*12+tg]);
        uint32_t h1=f2t(pw[(gid+8)*12+tg]);
        uint32_t h2=f2t(pw[gid*12+tg+4]);
        uint32_t h3=f2t(pw[(gid+8)*12+tg+4]);
        #pragma unroll
        for(int nt=0;nt<16;nt++){
            uint32_t b0=f2t(Vp[tg*128+nt*8+gid]);
            uint32_t b1=f2t(Vp[(tg+4)*128+nt*8+gid]);
            mma8(accO[nt],h0,h1,h2,h3,b0,b1);
        }
    }
    __syncthreads();

    // merge across 8 warps (scratch aliased onto Ks, now dead)
    for(int j=tid;j<2128;j+=256) sm[j]=0.f;
    __syncthreads();
    if(tg==0){ msh[warp*16+gid]=m0; msh[warp*16+gid+8]=m1; }
    __syncthreads();
    float M0=-1e30f,M1=-1e30f;
    #pragma unroll
    for(int w=0;w<8;w++){ M0=fmaxf(M0,msh[w*16+gid]); M1=fmaxf(M1,msh[w*16+gid+8]); }
    float sc0=ex2(m0-M0), sc1=ex2(m1-M1);
    if(tg==0){ atomicAdd(&Lsum[gid],l0*sc0); atomicAdd(&Lsum[gid+8],l1*sc1); }
    #pragma unroll
    for(int nt=0;nt<16;nt++){
        atomicAdd(&Osum[gid*132+nt*8+2*tg],       accO[nt][0]*sc0);
        atomicAdd(&Osum[gid*132+nt*8+2*tg+1],     accO[nt][1]*sc0);
        atomicAdd(&Osum[(gid+8)*132+nt*8+2*tg],   accO[nt][2]*sc1);
        atomicAdd(&Osum[(gid+8)*132+nt*8+2*tg+1], accO[nt][3]*sc1);
    }
    __syncthreads();
    int b=bh>>4, h=bh&15;
    for(int j=tid;j<2048;j+=256){
        int s_=j>>7, d=j&127;
        g_ao[(b*16+s_)*2048 + h*128 + d] = Osum[s_*132+d]/Lsum[s_];
    }
}

extern "C" void kernel_launch(void* const* d_in, const int* in_sizes, int n_in,
                              void* d_out, int out_size)
{
    const float* x =(const float*)d_in[0];
    const float* kc=(const float*)d_in[1];
    const float* vc=(const float*)d_in[2];
    const float* Wq=(const float*)d_in[3]; const float* bq=(const float*)d_in[4];
    const float* Wk=(const float*)d_in[5]; const float* bk=(const float*)d_in[6];
    const float* Wv=(const float*)d_in[7]; const float* bv=(const float*)d_in[8];
    const float* Wo=(const float*)d_in[9]; const float* bo=(const float*)d_in[10];
    cudaFuncSetAttribute(gemm_k<0>, cudaFuncAttributeMaxDynamicSharedMemorySize, GEMM_SMEM);
    cudaFuncSetAttribute(gemm_k<1>, cudaFuncAttributeMaxDynamicSharedMemorySize, GEMM_SMEM);
    cudaFuncSetAttribute(attn_k,    cudaFuncAttributeMaxDynamicSharedMemorySize, ATTN_SMEM);
    gemm_k<0><<<dim3(32,3),512,GEMM_SMEM>>>(x,Wq,Wk,Wv,bq,bk,bv);
    attn_k<<<128,256,ATTN_SMEM>>>(kc,vc);
    gemm_k<1><<<dim3(32,4),512,GEMM_SMEM>>>(nullptr,Wo,Wo,Wo,bo,bo,bo);
    reduce_k<<<128,512>>>(bo,(float*)d_out);
}

// round 13
// speedup vs baseline: 1.0816x; 1.0666x over previous
#include <cuda_runtime.h>
#include <cstdint>

#define DM 2048
static __device__ float g_q [128*2048];
static __device__ float g_kn[128*2048];
static __device__ float g_vn[128*2048];
static __device__ float g_ao[128*2048];
static __device__ float g_part[4*128*2048];

__device__ __forceinline__ uint32_t f2t(float x){
    uint32_t r; asm("cvt.rna.tf32.f32 %0,%1;":"=r"(r):"f"(x)); return r;
}
__device__ __forceinline__ float tf(float x){ return __uint_as_float(f2t(x)); }
__device__ __forceinline__ float ex2(float x){
    float r; asm("ex2.approx.ftz.f32 %0,%1;":"=f"(r):"f"(x)); return r;
}
__device__ __forceinline__ void mma8(float* c,uint32_t a0,uint32_t a1,uint32_t a2,uint32_t a3,
                                     uint32_t b0,uint32_t b1){
    asm volatile("mma.sync.aligned.m16n8k8.row.col.f32.tf32.tf32.f32 "
        "{%0,%1,%2,%3},{%4,%5,%6,%7},{%8,%9},{%0,%1,%2,%3};"
        :"+f"(c[0]),"+f"(c[1]),"+f"(c[2]),"+f"(c[3])
        :"r"(a0),"r"(a1),"r"(a2),"r"(a3),"r"(b0),"r"(b1));
}
__device__ __forceinline__ void cpa16(float* s, const float* g){
    uint32_t sa=(uint32_t)__cvta_generic_to_shared(s);
    asm volatile("cp.async.cg.shared.global [%0],[%1],16;" :: "r"(sa),"l"(g));
}
__device__ __forceinline__ void cpcommit(){ asm volatile("cp.async.commit_group;"); }
__device__ __forceinline__ void cpwait0(){ asm volatile("cp.async.wait_group 0;"); }
__device__ __forceinline__ void cpwait1(){ asm volatile("cp.async.wait_group 1;"); }

// ======================= GEMM: KC=64 chunks ===============================
// 512 threads, 16 warps (8M x 2N), warp tile 16x32, 2-stage cp.async.
// MODE0: x @ {Wq,Wk,Wv} + b -> scatter to g_q/g_kn/g_vn (sel = blockIdx.y).
// MODE1: g_ao @ Wo, K-slice blockIdx.y (512 wide) -> g_part (no bias).
#define XSTR 68
#define WSTR 72
#define XB (128*XSTR)
#define WB (64*WSTR)
#define GEMM_SMEM ((2*XB + 2*WB)*4)

template<int MODE>
__global__ __launch_bounds__(512) void gemm_k(const float* __restrict__ A,
    const float* __restrict__ W0,const float* __restrict__ W1,const float* __restrict__ W2,
    const float* __restrict__ B0,const float* __restrict__ B1,const float* __restrict__ B2)
{
    extern __shared__ float sm[];
    float* Xs = sm;             // [2][128*68]
    float* Ws = sm + 2*XB;      // [2][64*72]
    int tid=threadIdx.x, lane=tid&31, warp=tid>>5, tg=lane&3, gid=lane>>2;
    int sel = MODE? 0 : blockIdx.y;
    const float* W  = sel==0?W0: sel==1?W1:W2;
    const float* Bi = sel==0?B0: sel==1?B1:B2;
    const float* Ap = MODE? g_ao : A;
    int n0 = blockIdx.x*64;
    int kcb = MODE? blockIdx.y*8 : 0;   // chunk index base (chunks of 64)
    int kcn = MODE? 8 : 32;
    int m0 = (warp&7)*16, nb = (warp>>3)*32;
    float acc[4][4];
    #pragma unroll
    for(int i=0;i<4;i++){acc[i][0]=acc[i][1]=acc[i][2]=acc[i][3]=0.f;}

    auto issue=[&](int b,int kc){
        #pragma unroll
        for(int j=0;j<4;j++){ int id=tid+j*512; int r=id>>4, c4=(id&15)<<2;
            cpa16(&Xs[b*XB + r*XSTR + c4], &Ap[r*DM + kc*64 + c4]); }
        #pragma unroll
        for(int j=0;j<2;j++){ int id=tid+j*512; int r=id>>4, c4=(id&15)<<2;
            cpa16(&Ws[b*WB + r*WSTR + c4], &W[(kc*64+r)*DM + n0 + c4]); }
        cpcommit();
    };
    issue(0,kcb);
    for(int i=0;i<kcn;i++){
        if(i<kcn-1){ issue((i+1)&1, kcb+i+1); cpwait1(); } else cpwait0();
        __syncthreads();
        const float* xb = &Xs[(i&1)*XB];
        const float* wb = &Ws[(i&1)*WB];
        #pragma unroll
        for(int kk=0;kk<64;kk+=8){
            uint32_t a0=f2t(xb[(m0+gid)*XSTR+kk+tg]);
            uint32_t a1=f2t(xb[(m0+gid+8)*XSTR+kk+tg]);
            uint32_t a2=f2t(xb[(m0+gid)*XSTR+kk+tg+4]);
            uint32_t a3=f2t(xb[(m0+gid+8)*XSTR+kk+tg+4]);
            #pragma unroll
            for(int nt=0;nt<4;nt++){
                uint32_t b0=f2t(wb[(kk+tg)*WSTR+nb+nt*8+gid]);
                uint32_t b1=f2t(wb[(kk+tg+4)*WSTR+nb+nt*8+gid]);
                mma8(acc[nt],a0,a1,a2,a3,b0,b1);
            }
        }
        __syncthreads();
    }
    #pragma unroll
    for(int nt=0;nt<4;nt++){
        #pragma unroll
        for(int c=0;c<4;c++){
            int row=m0+gid+((c>>1)<<3);
            int col=n0+nb+nt*8+2*tg+(c&1);
            if(MODE){
                g_part[blockIdx.y*262144 + row*DM + col] = acc[nt][c];
            }else{
                float v=acc[nt][c]+Bi[col];
                float* dst = sel==0?g_q: sel==1?g_kn:g_vn;
                dst[(((row>>4)<<4)|(col>>7))*2048 + (row&15)*128 + (col&127)] = v;
            }
        }
    }
}

__global__ __launch_bounds__(512) void reduce_k(const float* __restrict__ Bo,
                                                float* __restrict__ O)
{
    int idx = blockIdx.x*512 + threadIdx.x;
    int base = idx*4, col = base & 2047;
    float4 p0=*(const float4*)&g_part[base];
    float4 p1=*(const float4*)&g_part[262144+base];
    float4 p2=*(const float4*)&g_part[524288+base];
    float4 p3=*(const float4*)&g_part[786432+base];
    float4 b=*(const float4*)&Bo[col];
    float4 o;
    o.x=p0.x+p1.x+p2.x+p3.x+b.x; o.y=p0.y+p1.y+p2.y+p3.y+b.y;
    o.z=p0.z+p1.z+p2.z+p3.z+b.z; o.w=p0.w+p1.w+p2.w+p3.w+b.w;
    *(float4*)&O[base]=o;
}

// ======================= Flash attention (round-9 schedule + dual-acc QK) =
// 1 CTA per (b,h), 8 warps. 64-key tiles, K+V double-buffered, TWO commit
// groups in flight (cpwait1), two barriers per tile. Warp w owns keys
// [8w,8w+8); private online softmax + 16x128 accO; merged at the end.
#define KS_STR 132
#define VS_STR 136
#define KBUF (64*KS_STR)
#define VBUF (64*VS_STR)
#define ATTN_SMEM ((2*KBUF + 2*VBUF + 16*132 + 8*192 + 16*132 + 16 + 8*16)*4)

__global__ __launch_bounds__(256) void attn_k(const float* __restrict__ kc_,
                                              const float* __restrict__ vc_)
{
    extern __shared__ float sm[];
    float* Ks   = sm;
    float* Vs   = sm + 2*KBUF;
    float* qs   = Vs + 2*VBUF;
    float* psm  = qs + 16*132;
    float* Osum = psm + 8*192;
    float* Lsum = Osum + 16*132;
    float* msh  = Lsum + 16;
    int tid=threadIdx.x, lane=tid&31, warp=tid>>5, tg=lane&3, gid=lane>>2;
    int bh=blockIdx.x;
    const float cs = 0.08838834764831843f * 1.4426950408889634f;
    #pragma unroll
    for(int j=tid;j<512;j+=256){
        float4 v=*(const float4*)&g_q[bh*2048+j*4];
        int r=j>>5, c4=(j&31)<<2;
        qs[r*132+c4+0]=tf(v.x*cs); qs[r*132+c4+1]=tf(v.y*cs);
        qs[r*132+c4+2]=tf(v.z*cs); qs[r*132+c4+3]=tf(v.w*cs);
    }
    for(int j=tid;j<16*132;j+=256) Osum[j]=0.f;
    if(tid<16) Lsum[tid]=0.f;
    const float* Kc = kc_ + (size_t)bh*4096*128;
    const float* Vc = vc_ + (size_t)bh*4096*128;

    auto issue=[&](int b,int t){
        #pragma unroll
        for(int j=0;j<8;j++){ int id=tid+j*256; int r=id>>5, c4=(id&31)<<2;
            cpa16(&Ks[b*KBUF + r*KS_STR + c4], &Kc[(size_t)(t*64+r)*128 + c4]); }
        #pragma unroll
        for(int j=0;j<8;j++){ int id=tid+j*256; int r=id>>5, c4=(id&31)<<2;
            cpa16(&Vs[b*VBUF + r*VS_STR + c4], &Vc[(size_t)(t*64+r)*128 + c4]); }
        cpcommit();
    };
    issue(0,0);
    __syncthreads();   // qs ready

    // hoist Q fragments to registers (rounded+scaled)
    uint32_t aq0[16],aq1[16],aq2[16],aq3[16];
    #pragma unroll
    for(int k8=0;k8<16;k8++){
        aq0[k8]=__float_as_uint(qs[gid*132+k8*8+tg]);
        aq1[k8]=__float_as_uint(qs[(gid+8)*132+k8*8+tg]);
        aq2[k8]=__float_as_uint(qs[gid*132+k8*8+tg+4]);
        aq3[k8]=__float_as_uint(qs[(gid+8)*132+k8*8+tg+4]);
    }

    float accO[16][4];
    #pragma unroll
    for(int i=0;i<16;i++){accO[i][0]=accO[i][1]=accO[i][2]=accO[i][3]=0.f;}
    float m0=-1e30f,m1=-1e30f,l0=0.f,l1=0.f;
    float* pw = psm + warp*192;

    for(int t=0;t<64;t++){
        if(t<63){ issue((t+1)&1, t+1); cpwait1(); } else cpwait0();
        __syncthreads();
        const float* Kb=&Ks[(t&1)*KBUF];
        const float* Vb=&Vs[(t&1)*VBUF];
        // QK with dual accumulators (halved mma RAW chain)
        float se[4]={0.f,0.f,0.f,0.f}, so[4]={0.f,0.f,0.f,0.f};
        #pragma unroll
        for(int k8=0;k8<16;k8+=2){
            uint32_t b0=f2t(Kb[(warp*8+gid)*KS_STR+k8*8+tg]);
            uint32_t b1=f2t(Kb[(warp*8+gid)*KS_STR+k8*8+tg+4]);
            mma8(se,aq0[k8],aq1[k8],aq2[k8],aq3[k8],b0,b1);
            uint32_t c0=f2t(Kb[(warp*8+gid)*KS_STR+(k8+1)*8+tg]);
            uint32_t c1=f2t(Kb[(warp*8+gid)*KS_STR+(k8+1)*8+tg+4]);
            mma8(so,aq0[k8+1],aq1[k8+1],aq2[k8+1],aq3[k8+1],c0,c1);
        }
        float s[4];
        #pragma unroll
        for(int c=0;c<4;c++) s[c]=se[c]+so[c];
        float x0=fmaxf(s[0],s[1]), x1=fmaxf(s[2],s[3]);
        x0=fmaxf(x0,__shfl_xor_sync(~0u,x0,1)); x0=fmaxf(x0,__shfl_xor_sync(~0u,x0,2));
        x1=fmaxf(x1,__shfl_xor_sync(~0u,x1,1)); x1=fmaxf(x1,__shfl_xor_sync(~0u,x1,2));
        bool upd = __any_sync(~0u,(x0>m0)||(x1>m1));
        float nm0=fmaxf(m0,x0), nm1=fmaxf(m1,x1);
        float f0=1.f,f1=1.f;
        if(upd){
            f0=ex2(m0-nm0); f1=ex2(m1-nm1);
            m0=nm0; m1=nm1;
            #pragma unroll
            for(int i=0;i<16;i++){accO[i][0]*=f0;accO[i][1]*=f0;accO[i][2]*=f1;accO[i][3]*=f1;}
        }
        float p0=ex2(s[0]-nm0), p1=ex2(s[1]-nm0);
        float p2=ex2(s[2]-nm1), p3=ex2(s[3]-nm1);
        float su0=p0+p1, su1=p2+p3;
        su0+=__shfl_xor_sync(~0u,su0,1); su0+=__shfl_xor_sync(~0u,su0,2);
        su1+=__shfl_xor_sync(~0u,su1,1); su1+=__shfl_xor_sync(~0u,su1,2);
        l0=l0*f0+su0; l1=l1*f1+su1;
        pw[gid*12+2*tg]=p0;     pw[gid*12+2*tg+1]=p1;
        pw[(gid+8)*12+2*tg]=p2; pw[(gid+8)*12+2*tg+1]=p3;
        __syncwarp();
        uint32_t h0=f2t(pw[gid*12+tg]);
        uint32_t h1=f2t(pw[(gid+8)*12+tg]);
        uint32_t h2=f2t(pw[gid*12+tg+4]);
        uint32_t h3=f2t(pw[(gid+8)*12+tg+4]);
        #pragma unroll
        for(int nt=0;nt<16;nt++){
            uint32_t b0=f2t(Vb[(warp*8+tg)*VS_STR+nt*8+gid]);
            uint32_t b1=f2t(Vb[(warp*8+tg+4)*VS_STR+nt*8+gid]);
            mma8(accO[nt],h0,h1,h2,h3,b0,b1);
        }
        __syncthreads();
    }

    // tail: 16 new keys (warps 0-1, 8 keys each) with causal mask
    if(warp<2){
        const float* Kp = g_kn + bh*2048 + warp*8*128;
        const float* Vp = g_vn + bh*2048 + warp*8*128;
        float s[4]={0.f,0.f,0.f,0.f};
        #pragma unroll
        for(int k8=0;k8<16;k8++){
            uint32_t b0=f2t(Kp[gid*128+k8*8+tg]);
            uint32_t b1=f2t(Kp[gid*128+k8*8+tg+4]);
            mma8(s,aq0[k8],aq1[k8],aq2[k8],aq3[k8],b0,b1);
        }
        #pragma unroll
        for(int c=0;c<4;c++){
            int col16=warp*8+2*tg+(c&1), row=gid+((c>>1)<<3);
            if(col16>row) s[c]=-1e30f;
        }
        float x0=fmaxf(s[0],s[1]), x1=fmaxf(s[2],s[3]);
        x0=fmaxf(x0,__shfl_xor_sync(~0u,x0,1)); x0=fmaxf(x0,__shfl_xor_sync(~0u,x0,2));
        x1=fmaxf(x1,__shfl_xor_sync(~0u,x1,1)); x1=fmaxf(x1,__shfl_xor_sync(~0u,x1,2));
        float nm0=fmaxf(m0,x0), nm1=fmaxf(m1,x1);
        float f0=ex2(m0-nm0), f1=ex2(m1-nm1);
        m0=nm0; m1=nm1;
        float p0=ex2(s[0]-nm0), p1=ex2(s[1]-nm0);
        float p2=ex2(s[2]-nm1), p3=ex2(s[3]-nm1);
        float su0=p0+p1, su1=p2+p3;
        su0+=__shfl_xor_sync(~0u,su0,1); su0+=__shfl_xor_sync(~0u,su0,2);
        su1+=__shfl_xor_sync(~0u,su1,1); su1+=__shfl_xor_sync(~0u,su1,2);
        l0=l0*f0+su0; l1=l1*f1+su1;
        #pragma unroll
        for(int i=0;i<16;i++){accO[i][0]*=f0;accO[i][1]*=f0;accO[i][2]*=f1;accO[i][3]*=f1;}
        pw[gid*12+2*tg]=p0;     pw[gid*12+2*tg+1]=p1;
        pw[(gid+8)*12+2*tg]=p2; pw[(gid+8)*12+2*tg+1]=p3;
        __syncwarp();
        uint32_t h0=f2t(pw[gid*12+tg]);
        uint32_t h1=f2t(pw[(gid+8)*12+tg]);
        uint32_t h2=f2t(pw[gid*12+tg+4]);
        uint32_t h3=f2t(pw[(gid+8)*12+tg+4]);
        #pragma unroll
        for(int nt=0;nt<16;nt++){
            uint32_t b0=f2t(Vp[tg*128+nt*8+gid]);
            uint32_t b1=f2t(Vp[(tg+4)*128+nt*8+gid]);
            mma8(accO[nt],h0,h1,h2,h3,b0,b1);
        }
    }

    // merge across 8 warps
    if(tg==0){ msh[warp*16+gid]=m0; msh[warp*16+gid+8]=m1; }
    __syncthreads();
    float M0=-1e30f,M1=-1e30f;
    #pragma unroll
    for(int w=0;w<8;w++){ M0=fmaxf(M0,msh[w*16+gid]); M1=fmaxf(M1,msh[w*16+gid+8]); }
    float sc0=ex2(m0-M0), sc1=ex2(m1-M1);
    if(tg==0){ atomicAdd(&Lsum[gid],l0*sc0); atomicAdd(&Lsum[gid+8],l1*sc1); }
    #pragma unroll
    for(int nt=0;nt<16;nt++){
        atomicAdd(&Osum[gid*132+nt*8+2*tg],       accO[nt][0]*sc0);
        atomicAdd(&Osum[gid*132+nt*8+2*tg+1],     accO[nt][1]*sc0);
        atomicAdd(&Osum[(gid+8)*132+nt*8+2*tg],   accO[nt][2]*sc1);
        atomicAdd(&Osum[(gid+8)*132+nt*8+2*tg+1], accO[nt][3]*sc1);
    }
    __syncthreads();
    int b=bh>>4, h=bh&15;
    for(int j=tid;j<2048;j+=256){
        int s_=j>>7, d=j&127;
        g_ao[(b*16+s_)*2048 + h*128 + d] = Osum[s_*132+d]/Lsum[s_];
    }
}

extern "C" void kernel_launch(void* const* d_in, const int* in_sizes, int n_in,
                              void* d_out, int out_size)
{
    const float* x =(const float*)d_in[0];
    const float* kc=(const float*)d_in[1];
    const float* vc=(const float*)d_in[2];
    const float* Wq=(const float*)d_in[3]; const float* bq=(const float*)d_in[4];
    const float* Wk=(const float*)d_in[5]; const float* bk=(const float*)d_in[6];
    const float* Wv=(const float*)d_in[7]; const float* bv=(const float*)d_in[8];
    const float* Wo=(const float*)d_in[9]; const float* bo=(const float*)d_in[10];
    cudaFuncSetAttribute(gemm_k<0>, cudaFuncAttributeMaxDynamicSharedMemorySize, GEMM_SMEM);
    cudaFuncSetAttribute(gemm_k<1>, cudaFuncAttributeMaxDynamicSharedMemorySize, GEMM_SMEM);
    cudaFuncSetAttribute(attn_k,    cudaFuncAttributeMaxDynamicSharedMemorySize, ATTN_SMEM);
    gemm_k<0><<<dim3(32,3),512,GEMM_SMEM>>>(x,Wq,Wk,Wv,bq,bk,bv);
    attn_k<<<128,256,ATTN_SMEM>>>(kc,vc);
    gemm_k<1><<<dim3(32,4),512,GEMM_SMEM>>>(nullptr,Wo,Wo,Wo,bo,bo,bo);
    reduce_k<<<128,512>>>(bo,(float*)d_out);
}

// round 14
// speedup vs baseline: 1.1511x; 1.0643x over previous
#include <cuda_runtime.h>
#include <cstdint>

#define DM 2048
static __device__ float g_q [128*2048];
static __device__ float g_kn[128*2048];
static __device__ float g_vn[128*2048];
static __device__ float g_ao[128*2048];
static __device__ float g_part[4*128*2048];     // out-proj split-K partials
static __device__ float g_pqkv[12*128*2048];    // QKV split-K partials [sel*4+slice]

__device__ __forceinline__ uint32_t f2t(float x){
    uint32_t r; asm("cvt.rna.tf32.f32 %0,%1;":"=r"(r):"f"(x)); return r;
}
__device__ __forceinline__ float tf(float x){ return __uint_as_float(f2t(x)); }
__device__ __forceinline__ float ex2(float x){
    float r; asm("ex2.approx.ftz.f32 %0,%1;":"=f"(r):"f"(x)); return r;
}
__device__ __forceinline__ void mma8(float* c,uint32_t a0,uint32_t a1,uint32_t a2,uint32_t a3,
                                     uint32_t b0,uint32_t b1){
    asm volatile("mma.sync.aligned.m16n8k8.row.col.f32.tf32.tf32.f32 "
        "{%0,%1,%2,%3},{%4,%5,%6,%7},{%8,%9},{%0,%1,%2,%3};"
        :"+f"(c[0]),"+f"(c[1]),"+f"(c[2]),"+f"(c[3])
        :"r"(a0),"r"(a1),"r"(a2),"r"(a3),"r"(b0),"r"(b1));
}
__device__ __forceinline__ void cpa16(float* s, const float* g){
    uint32_t sa=(uint32_t)__cvta_generic_to_shared(s);
    asm volatile("cp.async.cg.shared.global [%0],[%1],16;" :: "r"(sa),"l"(g));
}
__device__ __forceinline__ void cpcommit(){ asm volatile("cp.async.commit_group;"); }
__device__ __forceinline__ void cpwait0(){ asm volatile("cp.async.wait_group 0;"); }
__device__ __forceinline__ void cpwait1(){ asm volatile("cp.async.wait_group 1;"); }

// ======================= GEMM (round-9 KC32 structure, split-K partials) ==
// 512 threads, 16 warps (8M x 2N), warp tile 16x32, 2-stage cp.async.
// MODE0: x @ {Wq,Wk,Wv}, slice=blockIdx.z (K=512 each) -> g_pqkv partials.
// MODE1: g_ao @ Wo, slice=blockIdx.y -> g_part partials.
#define GEMM_SMEM ((2*128*36 + 2*32*72)*4)

template<int MODE>
__global__ __launch_bounds__(512) void gemm_k(const float* __restrict__ A,
    const float* __restrict__ W0,const float* __restrict__ W1,const float* __restrict__ W2)
{
    extern __shared__ float sm[];
    float* Xs = sm;             // [2][128*36]
    float* Ws = sm + 2*4608;    // [2][32*72]
    int tid=threadIdx.x, lane=tid&31, warp=tid>>5, tg=lane&3, gid=lane>>2;
    int sel = MODE? 0 : blockIdx.y;
    int slice = MODE? blockIdx.y : blockIdx.z;
    const float* W  = sel==0?W0: sel==1?W1:W2;
    const float* Ap = MODE? g_ao : A;
    float* Out = MODE? (g_part + slice*262144)
                     : (g_pqkv + (sel*4+slice)*262144);
    int n0 = blockIdx.x*64;
    int kcb = slice*16;   // chunks of 32; 16 chunks = K slice of 512
    int m0 = (warp&7)*16, nb = (warp>>3)*32;
    float acc[4][4];
    #pragma unroll
    for(int i=0;i<4;i++){acc[i][0]=acc[i][1]=acc[i][2]=acc[i][3]=0.f;}

    auto issue=[&](int b,int kc){
        #pragma unroll
        for(int j=0;j<2;j++){ int id=tid+j*512; int r=id>>3, c4=(id&7)<<2;
            cpa16(&Xs[b*4608 + r*36 + c4], &Ap[r*DM + kc*32 + c4]); }
        { int r=tid>>4, c4=(tid&15)<<2;
            cpa16(&Ws[b*2304 + r*72 + c4], &W[(kc*32+r)*DM + n0 + c4]); }
        cpcommit();
    };
    issue(0,kcb);
    for(int i=0;i<16;i++){
        if(i<15){ issue((i+1)&1, kcb+i+1); cpwait1(); } else cpwait0();
        __syncthreads();
        const float* xb = &Xs[(i&1)*4608];
        const float* wb = &Ws[(i&1)*2304];
        #pragma unroll
        for(int kk=0;kk<32;kk+=8){
            uint32_t a0=f2t(xb[(m0+gid)*36+kk+tg]);
            uint32_t a1=f2t(xb[(m0+gid+8)*36+kk+tg]);
            uint32_t a2=f2t(xb[(m0+gid)*36+kk+tg+4]);
            uint32_t a3=f2t(xb[(m0+gid+8)*36+kk+tg+4]);
            #pragma unroll
            for(int nt=0;nt<4;nt++){
                uint32_t b0=f2t(wb[(kk+tg)*72+nb+nt*8+gid]);
                uint32_t b1=f2t(wb[(kk+tg+4)*72+nb+nt*8+gid]);
                mma8(acc[nt],a0,a1,a2,a3,b0,b1);
            }
        }
        __syncthreads();
    }
    #pragma unroll
    for(int nt=0;nt<4;nt++){
        #pragma unroll
        for(int c=0;c<4;c++){
            int row=m0+gid+((c>>1)<<3);
            int col=n0+nb+nt*8+2*tg+(c&1);
            Out[row*DM + col] = acc[nt][c];
        }
    }
}

// reduce QKV split-K partials + bias -> scattered per-head q/kn/vn
__global__ __launch_bounds__(512) void reduce_qkv(const float* __restrict__ Bq,
    const float* __restrict__ Bk, const float* __restrict__ Bv)
{
    int idx = blockIdx.x*512 + threadIdx.x;   // 196608 float4 total
    int sel = idx>>16;                         // 65536 float4 per sel
    int rem = idx&65535;
    int base = rem*4;
    int row = base>>11, col = base&2047;
    const float* P = g_pqkv + sel*4*262144;
    float4 p0=*(const float4*)&P[base];
    float4 p1=*(const float4*)&P[262144+base];
    float4 p2=*(const float4*)&P[524288+base];
    float4 p3=*(const float4*)&P[786432+base];
    const float* Bi = sel==0?Bq: sel==1?Bk:Bv;
    float4 b=*(const float4*)&Bi[col];
    float4 o;
    o.x=p0.x+p1.x+p2.x+p3.x+b.x; o.y=p0.y+p1.y+p2.y+p3.y+b.y;
    o.z=p0.z+p1.z+p2.z+p3.z+b.z; o.w=p0.w+p1.w+p2.w+p3.w+b.w;
    float* dst = sel==0?g_q: sel==1?g_kn:g_vn;
    int off = (((row>>4)<<4)|(col>>7))*2048 + (row&15)*128 + (col&127);
    *(float4*)&dst[off]=o;
}

// reduce out-proj split-K partials + bias -> d_out
__global__ __launch_bounds__(512) void reduce_k(const float* __restrict__ Bo,
                                                float* __restrict__ O)
{
    int idx = blockIdx.x*512 + threadIdx.x;
    int base = idx*4, col = base & 2047;
    float4 p0=*(const float4*)&g_part[base];
    float4 p1=*(const float4*)&g_part[262144+base];
    float4 p2=*(const float4*)&g_part[524288+base];
    float4 p3=*(const float4*)&g_part[786432+base];
    float4 b=*(const float4*)&Bo[col];
    float4 o;
    o.x=p0.x+p1.x+p2.x+p3.x+b.x; o.y=p0.y+p1.y+p2.y+p3.y+b.y;
    o.z=p0.z+p1.z+p2.z+p3.z+b.z; o.w=p0.w+p1.w+p2.w+p3.w+b.w;
    *(float4*)&O[base]=o;
}

// ======================= Flash attention (round-9 EXACT) ==================
#define KS_STR 132
#define VS_STR 136
#define KBUF (64*KS_STR)
#define VBUF (64*VS_STR)
#define ATTN_SMEM ((2*KBUF + 2*VBUF + 16*132 + 8*192 + 16*132 + 16 + 8*16)*4)

__global__ __launch_bounds__(256) void attn_k(const float* __restrict__ kc_,
                                              const float* __restrict__ vc_)
{
    extern __shared__ float sm[];
    float* Ks   = sm;
    float* Vs   = sm + 2*KBUF;
    float* qs   = Vs + 2*VBUF;
    float* psm  = qs + 16*132;
    float* Osum = psm + 8*192;
    float* Lsum = Osum + 16*132;
    float* msh  = Lsum + 16;
    int tid=threadIdx.x, lane=tid&31, warp=tid>>5, tg=lane&3, gid=lane>>2;
    int bh=blockIdx.x;
    const float cs = 0.08838834764831843f * 1.4426950408889634f;
    #pragma unroll
    for(int j=tid;j<512;j+=256){
        float4 v=*(const float4*)&g_q[bh*2048+j*4];
        int r=j>>5, c4=(j&31)<<2;
        qs[r*132+c4+0]=tf(v.x*cs); qs[r*132+c4+1]=tf(v.y*cs);
        qs[r*132+c4+2]=tf(v.z*cs); qs[r*132+c4+3]=tf(v.w*cs);
    }
    for(int j=tid;j<16*132;j+=256) Osum[j]=0.f;
    if(tid<16) Lsum[tid]=0.f;
    const float* Kc = kc_ + (size_t)bh*4096*128;
    const float* Vc = vc_ + (size_t)bh*4096*128;

    auto issue=[&](int b,int t){
        #pragma unroll
        for(int j=0;j<8;j++){ int id=tid+j*256; int r=id>>5, c4=(id&31)<<2;
            cpa16(&Ks[b*KBUF + r*KS_STR + c4], &Kc[(size_t)(t*64+r)*128 + c4]); }
        #pragma unroll
        for(int j=0;j<8;j++){ int id=tid+j*256; int r=id>>5, c4=(id&31)<<2;
            cpa16(&Vs[b*VBUF + r*VS_STR + c4], &Vc[(size_t)(t*64+r)*128 + c4]); }
        cpcommit();
    };
    issue(0,0);
    __syncthreads();   // qs ready

    uint32_t aq0[16],aq1[16],aq2[16],aq3[16];
    #pragma unroll
    for(int k8=0;k8<16;k8++){
        aq0[k8]=__float_as_uint(qs[gid*132+k8*8+tg]);
        aq1[k8]=__float_as_uint(qs[(gid+8)*132+k8*8+tg]);
        aq2[k8]=__float_as_uint(qs[gid*132+k8*8+tg+4]);
        aq3[k8]=__float_as_uint(qs[(gid+8)*132+k8*8+tg+4]);
    }

    float accO[16][4];
    #pragma unroll
    for(int i=0;i<16;i++){accO[i][0]=accO[i][1]=accO[i][2]=accO[i][3]=0.f;}
    float m0=-1e30f,m1=-1e30f,l0=0.f,l1=0.f;
    float* pw = psm + warp*192;

    for(int t=0;t<64;t++){
        if(t<63){ issue((t+1)&1, t+1); cpwait1(); } else cpwait0();
        __syncthreads();
        const float* Kb=&Ks[(t&1)*KBUF];
        const float* Vb=&Vs[(t&1)*VBUF];
        float s[4]={0.f,0.f,0.f,0.f};
        #pragma unroll
        for(int k8=0;k8<16;k8++){
            uint32_t b0=f2t(Kb[(warp*8+gid)*KS_STR+k8*8+tg]);
            uint32_t b1=f2t(Kb[(warp*8+gid)*KS_STR+k8*8+tg+4]);
            mma8(s,aq0[k8],aq1[k8],aq2[k8],aq3[k8],b0,b1);
        }
        float x0=fmaxf(s[0],s[1]), x1=fmaxf(s[2],s[3]);
        x0=fmaxf(x0,__shfl_xor_sync(~0u,x0,1)); x0=fmaxf(x0,__shfl_xor_sync(~0u,x0,2));
        x1=fmaxf(x1,__shfl_xor_sync(~0u,x1,1)); x1=fmaxf(x1,__shfl_xor_sync(~0u,x1,2));
        bool upd = __any_sync(~0u,(x0>m0)||(x1>m1));
        float nm0=fmaxf(m0,x0), nm1=fmaxf(m1,x1);
        float f0=1.f,f1=1.f;
        if(upd){
            f0=ex2(m0-nm0); f1=ex2(m1-nm1);
            m0=nm0; m1=nm1;
            #pragma unroll
            for(int i=0;i<16;i++){accO[i][0]*=f0;accO[i][1]*=f0;accO[i][2]*=f1;accO[i][3]*=f1;}
        }
        float p0=ex2(s[0]-nm0), p1=ex2(s[1]-nm0);
        float p2=ex2(s[2]-nm1), p3=ex2(s[3]-nm1);
        float su0=p0+p1, su1=p2+p3;
        su0+=__shfl_xor_sync(~0u,su0,1); su0+=__shfl_xor_sync(~0u,su0,2);
        su1+=__shfl_xor_sync(~0u,su1,1); su1+=__shfl_xor_sync(~0u,su1,2);
        l0=l0*f0+su0; l1=l1*f1+su1;
        pw[gid*12+2*tg]=p0;     pw[gid*12+2*tg+1]=p1;
        pw[(gid+8)*12+2*tg]=p2; pw[(gid+8)*12+2*tg+1]=p3;
        __syncwarp();
        uint32_t h0=f2t(pw[gid*12+tg]);
        uint32_t h1=f2t(pw[(gid+8)*12+tg]);
        uint32_t h2=f2t(pw[gid*12+tg+4]);
        uint32_t h3=f2t(pw[(gid+8)*12+tg+4]);
        #pragma unroll
        for(int nt=0;nt<16;nt++){
            uint32_t b0=f2t(Vb[(warp*8+tg)*VS_STR+nt*8+gid]);
            uint32_t b1=f2t(Vb[(warp*8+tg+4)*VS_STR+nt*8+gid]);
            mma8(accO[nt],h0,h1,h2,h3,b0,b1);
        }
        __syncthreads();
    }

    if(warp<2){
        const float* Kp = g_kn + bh*2048 + warp*8*128;
        const float* Vp = g_vn + bh*2048 + warp*8*128;
        float s[4]={0.f,0.f,0.f,0.f};
        #pragma unroll
        for(int k8=0;k8<16;k8++){
            uint32_t b0=f2t(Kp[gid*128+k8*8+tg]);
            uint32_t b1=f2t(Kp[gid*128+k8*8+tg+4]);
            mma8(s,aq0[k8],aq1[k8],aq2[k8],aq3[k8],b0,b1);
        }
        #pragma unroll
        for(int c=0;c<4;c++){
            int col16=warp*8+2*tg+(c&1), row=gid+((c>>1)<<3);
            if(col16>row) s[c]=-1e30f;
        }
        float x0=fmaxf(s[0],s[1]), x1=fmaxf(s[2],s[3]);
        x0=fmaxf(x0,__shfl_xor_sync(~0u,x0,1)); x0=fmaxf(x0,__shfl_xor_sync(~0u,x0,2));
        x1=fmaxf(x1,__shfl_xor_sync(~0u,x1,1)); x1=fmaxf(x1,__shfl_xor_sync(~0u,x1,2));
        float nm0=fmaxf(m0,x0), nm1=fmaxf(m1,x1);
        float f0=ex2(m0-nm0), f1=ex2(m1-nm1);
        m0=nm0; m1=nm1;
        float p0=ex2(s[0]-nm0), p1=ex2(s[1]-nm0);
        float p2=ex2(s[2]-nm1), p3=ex2(s[3]-nm1);
        float su0=p0+p1, su1=p2+p3;
        su0+=__shfl_xor_sync(~0u,su0,1); su0+=__shfl_xor_sync(~0u,su0,2);
        su1+=__shfl_xor_sync(~0u,su1,1); su1+=__shfl_xor_sync(~0u,su1,2);
        l0=l0*f0+su0; l1=l1*f1+su1;
        #pragma unroll
        for(int i=0;i<16;i++){accO[i][0]*=f0;accO[i][1]*=f0;accO[i][2]*=f1;accO[i][3]*=f1;}
        pw[gid*12+2*tg]=p0;     pw[gid*12+2*tg+1]=p1;
        pw[(gid+8)*12+2*tg]=p2; pw[(gid+8)*12+2*tg+1]=p3;
        __syncwarp();
        uint32_t h0=f2t(pw[gid*12+tg]);
        uint32_t h1=f2t(pw[(gid+8)*12+tg]);
        uint32_t h2=f2t(pw[gid*12+tg+4]);
        uint32_t h3=f2t(pw[(gid+8)*12+tg+4]);
        #pragma unroll
        for(int nt=0;nt<16;nt++){
            uint32_t b0=f2t(Vp[tg*128+nt*8+gid]);
            uint32_t b1=f2t(Vp[(tg+4)*128+nt*8+gid]);
            mma8(accO[nt],h0,h1,h2,h3,b0,b1);
        }
    }

    if(tg==0){ msh[warp*16+gid]=m0; msh[warp*16+gid+8]=m1; }
    __syncthreads();
    float M0=-1e30f,M1=-1e30f;
    #pragma unroll
    for(int w=0;w<8;w++){ M0=fmaxf(M0,msh[w*16+gid]); M1=fmaxf(M1,msh[w*16+gid+8]); }
    float sc0=ex2(m0-M0), sc1=ex2(m1-M1);
    if(tg==0){ atomicAdd(&Lsum[gid],l0*sc0); atomicAdd(&Lsum[gid+8],l1*sc1); }
    #pragma unroll
    for(int nt=0;nt<16;nt++){
        atomicAdd(&Osum[gid*132+nt*8+2*tg],       accO[nt][0]*sc0);
        atomicAdd(&Osum[gid*132+nt*8+2*tg+1],     accO[nt][1]*sc0);
        atomicAdd(&Osum[(gid+8)*132+nt*8+2*tg],   accO[nt][2]*sc1);
        atomicAdd(&Osum[(gid+8)*132+nt*8+2*tg+1], accO[nt][3]*sc1);
    }
    __syncthreads();
    int b=bh>>4, h=bh&15;
    for(int j=tid;j<2048;j+=256){
        int s_=j>>7, d=j&127;
        g_ao[(b*16+s_)*2048 + h*128 + d] = Osum[s_*132+d]/Lsum[s_];
    }
}

extern "C" void kernel_launch(void* const* d_in, const int* in_sizes, int n_in,
                              void* d_out, int out_size)
{
    const float* x =(const float*)d_in[0];
    const float* kc=(const float*)d_in[1];
    const float* vc=(const float*)d_in[2];
    const float* Wq=(const float*)d_in[3]; const float* bq=(const float*)d_in[4];
    const float* Wk=(const float*)d_in[5]; const float* bk=(const float*)d_in[6];
    const float* Wv=(const float*)d_in[7]; const float* bv=(const float*)d_in[8];
    const float* Wo=(const float*)d_in[9]; const float* bo=(const float*)d_in[10];
    cudaFuncSetAttribute(gemm_k<0>, cudaFuncAttributeMaxDynamicSharedMemorySize, GEMM_SMEM);
    cudaFuncSetAttribute(gemm_k<1>, cudaFuncAttributeMaxDynamicSharedMemorySize, GEMM_SMEM);
    cudaFuncSetAttribute(attn_k,    cudaFuncAttributeMaxDynamicSharedMemorySize, ATTN_SMEM);
    gemm_k<0><<<dim3(32,3,4),512,GEMM_SMEM>>>(x,Wq,Wk,Wv);
    reduce_qkv<<<384,512>>>(bq,bk,bv);
    attn_k<<<128,256,ATTN_SMEM>>>(kc,vc);
    gemm_k<1><<<dim3(32,4),512,GEMM_SMEM>>>(nullptr,Wo,Wo,Wo);
    reduce_k<<<128,512>>>(bo,(float*)d_out);
}

// round 15
// speedup vs baseline: 1.1956x; 1.0386x over previous
#include <cuda_runtime.h>
#include <cstdint>

#define DM 2048
static __device__ float g_q [128*2048];
static __device__ float g_kn[128*2048];
static __device__ float g_vn[128*2048];
static __device__ float g_ao[128*2048];
static __device__ float g_part[8*128*2048];     // out-proj split-K partials (8 slices)
static __device__ float g_pqkv[9*128*2048];     // QKV split-K partials [sel*3+slice]

__device__ __forceinline__ uint32_t f2t(float x){
    uint32_t r; asm("cvt.rna.tf32.f32 %0,%1;":"=r"(r):"f"(x)); return r;
}
__device__ __forceinline__ float tf(float x){ return __uint_as_float(f2t(x)); }
__device__ __forceinline__ float ex2(float x){
    float r; asm("ex2.approx.ftz.f32 %0,%1;":"=f"(r):"f"(x)); return r;
}
__device__ __forceinline__ void mma8(float* c,uint32_t a0,uint32_t a1,uint32_t a2,uint32_t a3,
                                     uint32_t b0,uint32_t b1){
    asm volatile("mma.sync.aligned.m16n8k8.row.col.f32.tf32.tf32.f32 "
        "{%0,%1,%2,%3},{%4,%5,%6,%7},{%8,%9},{%0,%1,%2,%3};"
        :"+f"(c[0]),"+f"(c[1]),"+f"(c[2]),"+f"(c[3])
        :"r"(a0),"r"(a1),"r"(a2),"r"(a3),"r"(b0),"r"(b1));
}
__device__ __forceinline__ void cpa16(float* s, const float* g){
    uint32_t sa=(uint32_t)__cvta_generic_to_shared(s);
    asm volatile("cp.async.cg.shared.global [%0],[%1],16;" :: "r"(sa),"l"(g));
}
__device__ __forceinline__ void cpcommit(){ asm volatile("cp.async.commit_group;"); }
__device__ __forceinline__ void cpwait0(){ asm volatile("cp.async.wait_group 0;"); }
__device__ __forceinline__ void cpwait1(){ asm volatile("cp.async.wait_group 1;"); }

// ======================= GEMM (KC32, 2-stage cp.async, split-K partials) ==
// 512 threads, 16 warps (8M x 2N), warp tile 16x32.
// MODE0: x @ {Wq,Wk,Wv}, sel=blockIdx.y, slice=blockIdx.z (3 slices: 22/21/21
//        chunks of K=32) -> g_pqkv partials.
// MODE1: g_ao @ Wo, slice=blockIdx.y (8 slices x 8 chunks) -> g_part.
#define GEMM_SMEM ((2*128*36 + 2*32*72)*4)

template<int MODE>
__global__ __launch_bounds__(512) void gemm_k(const float* __restrict__ A,
    const float* __restrict__ W0,const float* __restrict__ W1,const float* __restrict__ W2)
{
    extern __shared__ float sm[];
    float* Xs = sm;             // [2][128*36]
    float* Ws = sm + 2*4608;    // [2][32*72]
    int tid=threadIdx.x, lane=tid&31, warp=tid>>5, tg=lane&3, gid=lane>>2;
    int sel = MODE? 0 : blockIdx.y;
    const float* W  = sel==0?W0: sel==1?W1:W2;
    const float* Ap = MODE? g_ao : A;
    int kcb, kcn;
    float* Out;
    if(MODE){
        int sl = blockIdx.y;
        kcb = sl*8; kcn = 8;
        Out = g_part + sl*262144;
    }else{
        int sl = blockIdx.z;
        kcb = (sl==0)?0:((sl==1)?22:43);
        kcn = (sl==0)?22:21;
        Out = g_pqkv + (sel*3+sl)*262144;
    }
    int n0 = blockIdx.x*64;
    int m0 = (warp&7)*16, nb = (warp>>3)*32;
    float acc[4][4];
    #pragma unroll
    for(int i=0;i<4;i++){acc[i][0]=acc[i][1]=acc[i][2]=acc[i][3]=0.f;}

    auto issue=[&](int b,int kc){
        #pragma unroll
        for(int j=0;j<2;j++){ int id=tid+j*512; int r=id>>3, c4=(id&7)<<2;
            cpa16(&Xs[b*4608 + r*36 + c4], &Ap[r*DM + kc*32 + c4]); }
        { int r=tid>>4, c4=(tid&15)<<2;
            cpa16(&Ws[b*2304 + r*72 + c4], &W[(kc*32+r)*DM + n0 + c4]); }
        cpcommit();
    };
    issue(0,kcb);
    for(int i=0;i<kcn;i++){
        if(i<kcn-1){ issue((i+1)&1, kcb+i+1); cpwait1(); } else cpwait0();
        __syncthreads();
        const float* xb = &Xs[(i&1)*4608];
        const float* wb = &Ws[(i&1)*2304];
        #pragma unroll
        for(int kk=0;kk<32;kk+=8){
            uint32_t a0=f2t(xb[(m0+gid)*36+kk+tg]);
            uint32_t a1=f2t(xb[(m0+gid+8)*36+kk+tg]);
            uint32_t a2=f2t(xb[(m0+gid)*36+kk+tg+4]);
            uint32_t a3=f2t(xb[(m0+gid+8)*36+kk+tg+4]);
            #pragma unroll
            for(int nt=0;nt<4;nt++){
                uint32_t b0=f2t(wb[(kk+tg)*72+nb+nt*8+gid]);
                uint32_t b1=f2t(wb[(kk+tg+4)*72+nb+nt*8+gid]);
                mma8(acc[nt],a0,a1,a2,a3,b0,b1);
            }
        }
        __syncthreads();
    }
    #pragma unroll
    for(int nt=0;nt<4;nt++){
        #pragma unroll
        for(int c=0;c<4;c++){
            int row=m0+gid+((c>>1)<<3);
            int col=n0+nb+nt*8+2*tg+(c&1);
            Out[row*DM + col] = acc[nt][c];
        }
    }
}

// reduce QKV split-K partials (3 slices) + bias -> scattered per-head q/kn/vn
__global__ __launch_bounds__(512) void reduce_qkv(const float* __restrict__ Bq,
    const float* __restrict__ Bk, const float* __restrict__ Bv)
{
    int idx = blockIdx.x*512 + threadIdx.x;   // 196608 float4 total
    int sel = idx>>16;
    int rem = idx&65535;
    int base = rem*4;
    int row = base>>11, col = base&2047;
    const float* P = g_pqkv + sel*3*262144;
    float4 p0=*(const float4*)&P[base];
    float4 p1=*(const float4*)&P[262144+base];
    float4 p2=*(const float4*)&P[524288+base];
    const float* Bi = sel==0?Bq: sel==1?Bk:Bv;
    float4 b=*(const float4*)&Bi[col];
    float4 o;
    o.x=p0.x+p1.x+p2.x+b.x; o.y=p0.y+p1.y+p2.y+b.y;
    o.z=p0.z+p1.z+p2.z+b.z; o.w=p0.w+p1.w+p2.w+b.w;
    float* dst = sel==0?g_q: sel==1?g_kn:g_vn;
    int off = (((row>>4)<<4)|(col>>7))*2048 + (row&15)*128 + (col&127);
    *(float4*)&dst[off]=o;
}

// reduce out-proj split-K partials (8 slices) + bias -> d_out
__global__ __launch_bounds__(512) void reduce_k(const float* __restrict__ Bo,
                                                float* __restrict__ O)
{
    int idx = blockIdx.x*512 + threadIdx.x;
    int base = idx*4, col = base & 2047;
    float4 a0=*(const float4*)&g_part[0*262144+base];
    float4 a1=*(const float4*)&g_part[1*262144+base];
    float4 a2=*(const float4*)&g_part[2*262144+base];
    float4 a3=*(const float4*)&g_part[3*262144+base];
    float4 a4=*(const float4*)&g_part[4*262144+base];
    float4 a5=*(const float4*)&g_part[5*262144+base];
    float4 a6=*(const float4*)&g_part[6*262144+base];
    float4 a7=*(const float4*)&g_part[7*262144+base];
    float4 b=*(const float4*)&Bo[col];
    float4 o;
    o.x=((a0.x+a1.x)+(a2.x+a3.x))+((a4.x+a5.x)+(a6.x+a7.x))+b.x;
    o.y=((a0.y+a1.y)+(a2.y+a3.y))+((a4.y+a5.y)+(a6.y+a7.y))+b.y;
    o.z=((a0.z+a1.z)+(a2.z+a3.z))+((a4.z+a5.z)+(a6.z+a7.z))+b.z;
    o.w=((a0.w+a1.w)+(a2.w+a3.w))+((a4.w+a5.w)+(a6.w+a7.w))+b.w;
    *(float4*)&O[base]=o;
}

// ======================= Flash attention (round-9 EXACT, frozen) ==========
#define KS_STR 132
#define VS_STR 136
#define KBUF (64*KS_STR)
#define VBUF (64*VS_STR)
#define ATTN_SMEM ((2*KBUF + 2*VBUF + 16*132 + 8*192 + 16*132 + 16 + 8*16)*4)

__global__ __launch_bounds__(256) void attn_k(const float* __restrict__ kc_,
                                              const float* __restrict__ vc_)
{
    extern __shared__ float sm[];
    float* Ks   = sm;
    float* Vs   = sm + 2*KBUF;
    float* qs   = Vs + 2*VBUF;
    float* psm  = qs + 16*132;
    float* Osum = psm + 8*192;
    float* Lsum = Osum + 16*132;
    float* msh  = Lsum + 16;
    int tid=threadIdx.x, lane=tid&31, warp=tid>>5, tg=lane&3, gid=lane>>2;
    int bh=blockIdx.x;
    const float cs = 0.08838834764831843f * 1.4426950408889634f;
    #pragma unroll
    for(int j=tid;j<512;j+=256){
        float4 v=*(const float4*)&g_q[bh*2048+j*4];
        int r=j>>5, c4=(j&31)<<2;
        qs[r*132+c4+0]=tf(v.x*cs); qs[r*132+c4+1]=tf(v.y*cs);
        qs[r*132+c4+2]=tf(v.z*cs); qs[r*132+c4+3]=tf(v.w*cs);
    }
    for(int j=tid;j<16*132;j+=256) Osum[j]=0.f;
    if(tid<16) Lsum[tid]=0.f;
    const float* Kc = kc_ + (size_t)bh*4096*128;
    const float* Vc = vc_ + (size_t)bh*4096*128;

    auto issue=[&](int b,int t){
        #pragma unroll
        for(int j=0;j<8;j++){ int id=tid+j*256; int r=id>>5, c4=(id&31)<<2;
            cpa16(&Ks[b*KBUF + r*KS_STR + c4], &Kc[(size_t)(t*64+r)*128 + c4]); }
        #pragma unroll
        for(int j=0;j<8;j++){ int id=tid+j*256; int r=id>>5, c4=(id&31)<<2;
            cpa16(&Vs[b*VBUF + r*VS_STR + c4], &Vc[(size_t)(t*64+r)*128 + c4]); }
        cpcommit();
    };
    issue(0,0);
    __syncthreads();   // qs ready

    uint32_t aq0[16],aq1[16],aq2[16],aq3[16];
    #pragma unroll
    for(int k8=0;k8<16;k8++){
        aq0[k8]=__float_as_uint(qs[gid*132+k8*8+tg]);
        aq1[k8]=__float_as_uint(qs[(gid+8)*132+k8*8+tg]);
        aq2[k8]=__float_as_uint(qs[gid*132+k8*8+tg+4]);
        aq3[k8]=__float_as_uint(qs[(gid+8)*132+k8*8+tg+4]);
    }

    float accO[16][4];
    #pragma unroll
    for(int i=0;i<16;i++){accO[i][0]=accO[i][1]=accO[i][2]=accO[i][3]=0.f;}
    float m0=-1e30f,m1=-1e30f,l0=0.f,l1=0.f;
    float* pw = psm + warp*192;

    for(int t=0;t<64;t++){
        if(t<63){ issue((t+1)&1, t+1); cpwait1(); } else cpwait0();
        __syncthreads();
        const float* Kb=&Ks[(t&1)*KBUF];
        const float* Vb=&Vs[(t&1)*VBUF];
        float s[4]={0.f,0.f,0.f,0.f};
        #pragma unroll
        for(int k8=0;k8<16;k8++){
            uint32_t b0=f2t(Kb[(warp*8+gid)*KS_STR+k8*8+tg]);
            uint32_t b1=f2t(Kb[(warp*8+gid)*KS_STR+k8*8+tg+4]);
            mma8(s,aq0[k8],aq1[k8],aq2[k8],aq3[k8],b0,b1);
        }
        float x0=fmaxf(s[0],s[1]), x1=fmaxf(s[2],s[3]);
        x0=fmaxf(x0,__shfl_xor_sync(~0u,x0,1)); x0=fmaxf(x0,__shfl_xor_sync(~0u,x0,2));
        x1=fmaxf(x1,__shfl_xor_sync(~0u,x1,1)); x1=fmaxf(x1,__shfl_xor_sync(~0u,x1,2));
        bool upd = __any_sync(~0u,(x0>m0)||(x1>m1));
        float nm0=fmaxf(m0,x0), nm1=fmaxf(m1,x1);
        float f0=1.f,f1=1.f;
        if(upd){
            f0=ex2(m0-nm0); f1=ex2(m1-nm1);
            m0=nm0; m1=nm1;
            #pragma unroll
            for(int i=0;i<16;i++){accO[i][0]*=f0;accO[i][1]*=f0;accO[i][2]*=f1;accO[i][3]*=f1;}
        }
        float p0=ex2(s[0]-nm0), p1=ex2(s[1]-nm0);
        float p2=ex2(s[2]-nm1), p3=ex2(s[3]-nm1);
        float su0=p0+p1, su1=p2+p3;
        su0+=__shfl_xor_sync(~0u,su0,1); su0+=__shfl_xor_sync(~0u,su0,2);
        su1+=__shfl_xor_sync(~0u,su1,1); su1+=__shfl_xor_sync(~0u,su1,2);
        l0=l0*f0+su0; l1=l1*f1+su1;
        pw[gid*12+2*tg]=p0;     pw[gid*12+2*tg+1]=p1;
        pw[(gid+8)*12+2*tg]=p2; pw[(gid+8)*12+2*tg+1]=p3;
        __syncwarp();
        uint32_t h0=f2t(pw[gid*12+tg]);
        uint32_t h1=f2t(pw[(gid+8)*12+tg]);
        uint32_t h2=f2t(pw[gid*12+tg+4]);
        uint32_t h3=f2t(pw[(gid+8)*12+tg+4]);
        #pragma unroll
        for(int nt=0;nt<16;nt++){
            uint32_t b0=f2t(Vb[(warp*8+tg)*VS_STR+nt*8+gid]);
            uint32_t b1=f2t(Vb[(warp*8+tg+4)*VS_STR+nt*8+gid]);
            mma8(accO[nt],h0,h1,h2,h3,b0,b1);
        }
        __syncthreads();
    }

    if(warp<2){
        const float* Kp = g_kn + bh*2048 + warp*8*128;
        const float* Vp = g_vn + bh*2048 + warp*8*128;
        float s[4]={0.f,0.f,0.f,0.f};
        #pragma unroll
        for(int k8=0;k8<16;k8++){
            uint32_t b0=f2t(Kp[gid*128+k8*8+tg]);
            uint32_t b1=f2t(Kp[gid*128+k8*8+tg+4]);
            mma8(s,aq0[k8],aq1[k8],aq2[k8],aq3[k8],b0,b1);
        }
        #pragma unroll
        for(int c=0;c<4;c++){
            int col16=warp*8+2*tg+(c&1), row=gid+((c>>1)<<3);
            if(col16>row) s[c]=-1e30f;
        }
        float x0=fmaxf(s[0],s[1]), x1=fmaxf(s[2],s[3]);
        x0=fmaxf(x0,__shfl_xor_sync(~0u,x0,1)); x0=fmaxf(x0,__shfl_xor_sync(~0u,x0,2));
        x1=fmaxf(x1,__shfl_xor_sync(~0u,x1,1)); x1=fmaxf(x1,__shfl_xor_sync(~0u,x1,2));
        float nm0=fmaxf(m0,x0), nm1=fmaxf(m1,x1);
        float f0=ex2(m0-nm0), f1=ex2(m1-nm1);
        m0=nm0; m1=nm1;
        float p0=ex2(s[0]-nm0), p1=ex2(s[1]-nm0);
        float p2=ex2(s[2]-nm1), p3=ex2(s[3]-nm1);
        float su0=p0+p1, su1=p2+p3;
        su0+=__shfl_xor_sync(~0u,su0,1); su0+=__shfl_xor_sync(~0u,su0,2);
        su1+=__shfl_xor_sync(~0u,su1,1); su1+=__shfl_xor_sync(~0u,su1,2);
        l0=l0*f0+su0; l1=l1*f1+su1;
        #pragma unroll
        for(int i=0;i<16;i++){accO[i][0]*=f0;accO[i][1]*=f0;accO[i][2]*=f1;accO[i][3]*=f1;}
        pw[gid*12+2*tg]=p0;     pw[gid*12+2*tg+1]=p1;
        pw[(gid+8)*12+2*tg]=p2; pw[(gid+8)*12+2*tg+1]=p3;
        __syncwarp();
        uint32_t h0=f2t(pw[gid*12+tg]);
        uint32_t h1=f2t(pw[(gid+8)*12+tg]);
        uint32_t h2=f2t(pw[gid*12+tg+4]);
        uint32_t h3=f2t(pw[(gid+8)*12+tg+4]);
        #pragma unroll
        for(int nt=0;nt<16;nt++){
            uint32_t b0=f2t(Vp[tg*128+nt*8+gid]);
            uint32_t b1=f2t(Vp[(tg+4)*128+nt*8+gid]);
            mma8(accO[nt],h0,h1,h2,h3,b0,b1);
        }
    }

    if(tg==0){ msh[warp*16+gid]=m0; msh[warp*16+gid+8]=m1; }
    __syncthreads();
    float M0=-1e30f,M1=-1e30f;
    #pragma unroll
    for(int w=0;w<8;w++){ M0=fmaxf(M0,msh[w*16+gid]); M1=fmaxf(M1,msh[w*16+gid+8]); }
    float sc0=ex2(m0-M0), sc1=ex2(m1-M1);
    if(tg==0){ atomicAdd(&Lsum[gid],l0*sc0); atomicAdd(&Lsum[gid+8],l1*sc1); }
    #pragma unroll
    for(int nt=0;nt<16;nt++){
        atomicAdd(&Osum[gid*132+nt*8+2*tg],       accO[nt][0]*sc0);
        atomicAdd(&Osum[gid*132+nt*8+2*tg+1],     accO[nt][1]*sc0);
        atomicAdd(&Osum[(gid+8)*132+nt*8+2*tg],   accO[nt][2]*sc1);
        atomicAdd(&Osum[(gid+8)*132+nt*8+2*tg+1], accO[nt][3]*sc1);
    }
    __syncthreads();
    int b=bh>>4, h=bh&15;
    for(int j=tid;j<2048;j+=256){
        int s_=j>>7, d=j&127;
        g_ao[(b*16+s_)*2048 + h*128 + d] = Osum[s_*132+d]/Lsum[s_];
    }
}

extern "C" void kernel_launch(void* const* d_in, const int* in_sizes, int n_in,
                              void* d_out, int out_size)
{
    const float* x =(const float*)d_in[0];
    const float* kc=(const float*)d_in[1];
    const float* vc=(const float*)d_in[2];
    const float* Wq=(const float*)d_in[3]; const float* bq=(const float*)d_in[4];
    const float* Wk=(const float*)d_in[5]; const float* bk=(const float*)d_in[6];
    const float* Wv=(const float*)d_in[7]; const float* bv=(const float*)d_in[8];
    const float* Wo=(const float*)d_in[9]; const float* bo=(const float*)d_in[10];
    cudaFuncSetAttribute(gemm_k<0>, cudaFuncAttributeMaxDynamicSharedMemorySize, GEMM_SMEM);
    cudaFuncSetAttribute(gemm_k<1>, cudaFuncAttributeMaxDynamicSharedMemorySize, GEMM_SMEM);
    cudaFuncSetAttribute(attn_k,    cudaFuncAttributeMaxDynamicSharedMemorySize, ATTN_SMEM);
    gemm_k<0><<<dim3(32,3,3),512,GEMM_SMEM>>>(x,Wq,Wk,Wv);
    reduce_qkv<<<384,512>>>(bq,bk,bv);
    attn_k<<<128,256,ATTN_SMEM>>>(kc,vc);
    gemm_k<1><<<dim3(32,8),512,GEMM_SMEM>>>(nullptr,Wo,Wo,Wo);
    reduce_k<<<128,512>>>(bo,(float*)d_out);
}

// round 16
// speedup vs baseline: 1.1983x; 1.0022x over previous
#include <cuda_runtime.h>
#include <cstdint>

#define DM 2048
static __device__ float g_q [128*2048];
static __device__ float g_kn[128*2048];
static __device__ float g_vn[128*2048];
static __device__ float g_ao[128*2048];
static __device__ float g_part[8*128*2048];     // out-proj split-K partials (8 slices)
static __device__ float g_pqkv[9*128*2048];     // QKV split-K partials [sel*3+slice]

__device__ __forceinline__ uint32_t f2t(float x){
    uint32_t r; asm("cvt.rna.tf32.f32 %0,%1;":"=r"(r):"f"(x)); return r;
}
__device__ __forceinline__ float tf(float x){ return __uint_as_float(f2t(x)); }
__device__ __forceinline__ float ex2(float x){
    float r; asm("ex2.approx.ftz.f32 %0,%1;":"=f"(r):"f"(x)); return r;
}
__device__ __forceinline__ void mma8(float* c,uint32_t a0,uint32_t a1,uint32_t a2,uint32_t a3,
                                     uint32_t b0,uint32_t b1){
    asm volatile("mma.sync.aligned.m16n8k8.row.col.f32.tf32.tf32.f32 "
        "{%0,%1,%2,%3},{%4,%5,%6,%7},{%8,%9},{%0,%1,%2,%3};"
        :"+f"(c[0]),"+f"(c[1]),"+f"(c[2]),"+f"(c[3])
        :"r"(a0),"r"(a1),"r"(a2),"r"(a3),"r"(b0),"r"(b1));
}
__device__ __forceinline__ void cpa16(float* s, const float* g){
    uint32_t sa=(uint32_t)__cvta_generic_to_shared(s);
    asm volatile("cp.async.cg.shared.global [%0],[%1],16;" :: "r"(sa),"l"(g));
}
__device__ __forceinline__ void cpcommit(){ asm volatile("cp.async.commit_group;"); }
__device__ __forceinline__ void cpwait0(){ asm volatile("cp.async.wait_group 0;"); }
__device__ __forceinline__ void cpwait1(){ asm volatile("cp.async.wait_group 1;"); }

// ======================= GEMM (round-15, frozen) ==========================
#define GEMM_SMEM ((2*128*36 + 2*32*72)*4)

template<int MODE>
__global__ __launch_bounds__(512) void gemm_k(const float* __restrict__ A,
    const float* __restrict__ W0,const float* __restrict__ W1,const float* __restrict__ W2)
{
    extern __shared__ float sm[];
    float* Xs = sm;
    float* Ws = sm + 2*4608;
    int tid=threadIdx.x, lane=tid&31, warp=tid>>5, tg=lane&3, gid=lane>>2;
    int sel = MODE? 0 : blockIdx.y;
    const float* W  = sel==0?W0: sel==1?W1:W2;
    const float* Ap = MODE? g_ao : A;
    int kcb, kcn;
    float* Out;
    if(MODE){
        int sl = blockIdx.y;
        kcb = sl*8; kcn = 8;
        Out = g_part + sl*262144;
    }else{
        int sl = blockIdx.z;
        kcb = (sl==0)?0:((sl==1)?22:43);
        kcn = (sl==0)?22:21;
        Out = g_pqkv + (sel*3+sl)*262144;
    }
    int n0 = blockIdx.x*64;
    int m0 = (warp&7)*16, nb = (warp>>3)*32;
    float acc[4][4];
    #pragma unroll
    for(int i=0;i<4;i++){acc[i][0]=acc[i][1]=acc[i][2]=acc[i][3]=0.f;}

    auto issue=[&](int b,int kc){
        #pragma unroll
        for(int j=0;j<2;j++){ int id=tid+j*512; int r=id>>3, c4=(id&7)<<2;
            cpa16(&Xs[b*4608 + r*36 + c4], &Ap[r*DM + kc*32 + c4]); }
        { int r=tid>>4, c4=(tid&15)<<2;
            cpa16(&Ws[b*2304 + r*72 + c4], &W[(kc*32+r)*DM + n0 + c4]); }
        cpcommit();
    };
    issue(0,kcb);
    for(int i=0;i<kcn;i++){
        if(i<kcn-1){ issue((i+1)&1, kcb+i+1); cpwait1(); } else cpwait0();
        __syncthreads();
        const float* xb = &Xs[(i&1)*4608];
        const float* wb = &Ws[(i&1)*2304];
        #pragma unroll
        for(int kk=0;kk<32;kk+=8){
            uint32_t a0=f2t(xb[(m0+gid)*36+kk+tg]);
            uint32_t a1=f2t(xb[(m0+gid+8)*36+kk+tg]);
            uint32_t a2=f2t(xb[(m0+gid)*36+kk+tg+4]);
            uint32_t a3=f2t(xb[(m0+gid+8)*36+kk+tg+4]);
            #pragma unroll
            for(int nt=0;nt<4;nt++){
                uint32_t b0=f2t(wb[(kk+tg)*72+nb+nt*8+gid]);
                uint32_t b1=f2t(wb[(kk+tg+4)*72+nb+nt*8+gid]);
                mma8(acc[nt],a0,a1,a2,a3,b0,b1);
            }
        }
        __syncthreads();
    }
    #pragma unroll
    for(int nt=0;nt<4;nt++){
        #pragma unroll
        for(int c=0;c<4;c++){
            int row=m0+gid+((c>>1)<<3);
            int col=n0+nb+nt*8+2*tg+(c&1);
            Out[row*DM + col] = acc[nt][c];
        }
    }
}

__global__ __launch_bounds__(512) void reduce_qkv(const float* __restrict__ Bq,
    const float* __restrict__ Bk, const float* __restrict__ Bv)
{
    int idx = blockIdx.x*512 + threadIdx.x;
    int sel = idx>>16;
    int rem = idx&65535;
    int base = rem*4;
    int row = base>>11, col = base&2047;
    const float* P = g_pqkv + sel*3*262144;
    float4 p0=*(const float4*)&P[base];
    float4 p1=*(const float4*)&P[262144+base];
    float4 p2=*(const float4*)&P[524288+base];
    const float* Bi = sel==0?Bq: sel==1?Bk:Bv;
    float4 b=*(const float4*)&Bi[col];
    float4 o;
    o.x=p0.x+p1.x+p2.x+b.x; o.y=p0.y+p1.y+p2.y+b.y;
    o.z=p0.z+p1.z+p2.z+b.z; o.w=p0.w+p1.w+p2.w+b.w;
    float* dst = sel==0?g_q: sel==1?g_kn:g_vn;
    int off = (((row>>4)<<4)|(col>>7))*2048 + (row&15)*128 + (col&127);
    *(float4*)&dst[off]=o;
}

__global__ __launch_bounds__(512) void reduce_k(const float* __restrict__ Bo,
                                                float* __restrict__ O)
{
    int idx = blockIdx.x*512 + threadIdx.x;
    int base = idx*4, col = base & 2047;
    float4 a0=*(const float4*)&g_part[0*262144+base];
    float4 a1=*(const float4*)&g_part[1*262144+base];
    float4 a2=*(const float4*)&g_part[2*262144+base];
    float4 a3=*(const float4*)&g_part[3*262144+base];
    float4 a4=*(const float4*)&g_part[4*262144+base];
    float4 a5=*(const float4*)&g_part[5*262144+base];
    float4 a6=*(const float4*)&g_part[6*262144+base];
    float4 a7=*(const float4*)&g_part[7*262144+base];
    float4 b=*(const float4*)&Bo[col];
    float4 o;
    o.x=((a0.x+a1.x)+(a2.x+a3.x))+((a4.x+a5.x)+(a6.x+a7.x))+b.x;
    o.y=((a0.y+a1.y)+(a2.y+a3.y))+((a4.y+a5.y)+(a6.y+a7.y))+b.y;
    o.z=((a0.z+a1.z)+(a2.z+a3.z))+((a4.z+a5.z)+(a6.z+a7.z))+b.z;
    o.w=((a0.w+a1.w)+(a2.w+a3.w))+((a4.w+a5.w)+(a6.w+a7.w))+b.w;
    *(float4*)&O[base]=o;
}

// ======================= Flash attention: 3-deep rings, 1 barrier/tile ====
#define KS_STR 132
#define VS_STR 136
#define KBUF (64*KS_STR)
#define VBUF (64*VS_STR)
#define ATTN_SMEM ((3*KBUF + 3*VBUF + 16*132 + 8*192)*4)

__global__ __launch_bounds__(256) void attn_k(const float* __restrict__ kc_,
                                              const float* __restrict__ vc_)
{
    extern __shared__ float sm[];
    float* Ks   = sm;                 // [3][64*132]
    float* Vs   = sm + 3*KBUF;        // [3][64*136]
    float* qs   = Vs + 3*VBUF;        // [16*132]
    float* psm  = qs + 16*132;        // [8][16*12]
    // merge scratch aliased onto Ks (dead after main loop):
    float* Osum = sm;                 // [16*132]
    float* Lsum = sm + 2112;          // [16]
    float* msh  = sm + 2128;          // [8][16]
    int tid=threadIdx.x, lane=tid&31, warp=tid>>5, tg=lane&3, gid=lane>>2;
    int bh=blockIdx.x;
    const float cs = 0.08838834764831843f * 1.4426950408889634f;
    #pragma unroll
    for(int j=tid;j<512;j+=256){
        float4 v=*(const float4*)&g_q[bh*2048+j*4];
        int r=j>>5, c4=(j&31)<<2;
        qs[r*132+c4+0]=tf(v.x*cs); qs[r*132+c4+1]=tf(v.y*cs);
        qs[r*132+c4+2]=tf(v.z*cs); qs[r*132+c4+3]=tf(v.w*cs);
    }
    const float* Kc = kc_ + (size_t)bh*4096*128;
    const float* Vc = vc_ + (size_t)bh*4096*128;

    auto issue=[&](int t){
        float* kd=&Ks[(t%3)*KBUF];
        float* vd=&Vs[(t%3)*VBUF];
        #pragma unroll
        for(int j=0;j<8;j++){ int id=tid+j*256; int r=id>>5, c4=(id&31)<<2;
            cpa16(&kd[r*KS_STR + c4], &Kc[(size_t)(t*64+r)*128 + c4]); }
        #pragma unroll
        for(int j=0;j<8;j++){ int id=tid+j*256; int r=id>>5, c4=(id&31)<<2;
            cpa16(&vd[r*VS_STR + c4], &Vc[(size_t)(t*64+r)*128 + c4]); }
        cpcommit();
    };
    issue(0); issue(1);
    __syncthreads();   // qs ready

    uint32_t aq0[16],aq1[16],aq2[16],aq3[16];
    #pragma unroll
    for(int k8=0;k8<16;k8++){
        aq0[k8]=__float_as_uint(qs[gid*132+k8*8+tg]);
        aq1[k8]=__float_as_uint(qs[(gid+8)*132+k8*8+tg]);
        aq2[k8]=__float_as_uint(qs[gid*132+k8*8+tg+4]);
        aq3[k8]=__float_as_uint(qs[(gid+8)*132+k8*8+tg+4]);
    }

    float accO[16][4];
    #pragma unroll
    for(int i=0;i<16;i++){accO[i][0]=accO[i][1]=accO[i][2]=accO[i][3]=0.f;}
    float m0=-1e30f,m1=-1e30f,l0=0.f,l1=0.f;
    float* pw = psm + warp*192;

    for(int t=0;t<64;t++){
        if(t<63) cpwait1(); else cpwait0();
        __syncthreads();             // single barrier per tile
        if(t+2<64) issue(t+2);
        const float* Kb=&Ks[(t%3)*KBUF];
        const float* Vb=&Vs[(t%3)*VBUF];
        float s[4]={0.f,0.f,0.f,0.f};
        #pragma unroll
        for(int k8=0;k8<16;k8++){
            uint32_t b0=f2t(Kb[(warp*8+gid)*KS_STR+k8*8+tg]);
            uint32_t b1=f2t(Kb[(warp*8+gid)*KS_STR+k8*8+tg+4]);
            mma8(s,aq0[k8],aq1[k8],aq2[k8],aq3[k8],b0,b1);
        }
        float x0=fmaxf(s[0],s[1]), x1=fmaxf(s[2],s[3]);
        x0=fmaxf(x0,__shfl_xor_sync(~0u,x0,1)); x0=fmaxf(x0,__shfl_xor_sync(~0u,x0,2));
        x1=fmaxf(x1,__shfl_xor_sync(~0u,x1,1)); x1=fmaxf(x1,__shfl_xor_sync(~0u,x1,2));
        bool upd = __any_sync(~0u,(x0>m0)||(x1>m1));
        float nm0=fmaxf(m0,x0), nm1=fmaxf(m1,x1);
        float f0=1.f,f1=1.f;
        if(upd){
            f0=ex2(m0-nm0); f1=ex2(m1-nm1);
            m0=nm0; m1=nm1;
            #pragma unroll
            for(int i=0;i<16;i++){accO[i][0]*=f0;accO[i][1]*=f0;accO[i][2]*=f1;accO[i][3]*=f1;}
        }
        float p0=ex2(s[0]-nm0), p1=ex2(s[1]-nm0);
        float p2=ex2(s[2]-nm1), p3=ex2(s[3]-nm1);
        float su0=p0+p1, su1=p2+p3;
        su0+=__shfl_xor_sync(~0u,su0,1); su0+=__shfl_xor_sync(~0u,su0,2);
        su1+=__shfl_xor_sync(~0u,su1,1); su1+=__shfl_xor_sync(~0u,su1,2);
        l0=l0*f0+su0; l1=l1*f1+su1;
        pw[gid*12+2*tg]=p0;     pw[gid*12+2*tg+1]=p1;
        pw[(gid+8)*12+2*tg]=p2; pw[(gid+8)*12+2*tg+1]=p3;
        __syncwarp();
        uint32_t h0=f2t(pw[gid*12+tg]);
        uint32_t h1=f2t(pw[(gid+8)*12+tg]);
        uint32_t h2=f2t(pw[gid*12+tg+4]);
        uint32_t h3=f2t(pw[(gid+8)*12+tg+4]);
        #pragma unroll
        for(int nt=0;nt<16;nt++){
            uint32_t b0=f2t(Vb[(warp*8+tg)*VS_STR+nt*8+gid]);
            uint32_t b1=f2t(Vb[(warp*8+tg+4)*VS_STR+nt*8+gid]);
            mma8(accO[nt],h0,h1,h2,h3,b0,b1);
        }
        __syncwarp();
    }
    __syncthreads();

    // tail: 16 new keys (warps 0-1, 8 keys each) with causal mask
    if(warp<2){
        const float* Kp = g_kn + bh*2048 + warp*8*128;
        const float* Vp = g_vn + bh*2048 + warp*8*128;
        float s[4]={0.f,0.f,0.f,0.f};
        #pragma unroll
        for(int k8=0;k8<16;k8++){
            uint32_t b0=f2t(Kp[gid*128+k8*8+tg]);
            uint32_t b1=f2t(Kp[gid*128+k8*8+tg+4]);
            mma8(s,aq0[k8],aq1[k8],aq2[k8],aq3[k8],b0,b1);
        }
        #pragma unroll
        for(int c=0;c<4;c++){
            int col16=warp*8+2*tg+(c&1), row=gid+((c>>1)<<3);
            if(col16>row) s[c]=-1e30f;
        }
        float x0=fmaxf(s[0],s[1]), x1=fmaxf(s[2],s[3]);
        x0=fmaxf(x0,__shfl_xor_sync(~0u,x0,1)); x0=fmaxf(x0,__shfl_xor_sync(~0u,x0,2));
        x1=fmaxf(x1,__shfl_xor_sync(~0u,x1,1)); x1=fmaxf(x1,__shfl_xor_sync(~0u,x1,2));
        float nm0=fmaxf(m0,x0), nm1=fmaxf(m1,x1);
        float f0=ex2(m0-nm0), f1=ex2(m1-nm1);
        m0=nm0; m1=nm1;
        float p0=ex2(s[0]-nm0), p1=ex2(s[1]-nm0);
        float p2=ex2(s[2]-nm1), p3=ex2(s[3]-nm1);
        float su0=p0+p1, su1=p2+p3;
        su0+=__shfl_xor_sync(~0u,su0,1); su0+=__shfl_xor_sync(~0u,su0,2);
        su1+=__shfl_xor_sync(~0u,su1,1); su1+=__shfl_xor_sync(~0u,su1,2);
        l0=l0*f0+su0; l1=l1*f1+su1;
        #pragma unroll
        for(int i=0;i<16;i++){accO[i][0]*=f0;accO[i][1]*=f0;accO[i][2]*=f1;accO[i][3]*=f1;}
        pw[gid*12+2*tg]=p0;     pw[gid*12+2*tg+1]=p1;
        pw[(gid+8)*12+2*tg]=p2; pw[(gid+8)*12+2*tg+1]=p3;
        __syncwarp();
        uint32_t h0=f2t(pw[gid*12+tg]);
        uint32_t h1=f2t(pw[(gid+8)*12+tg]);
        uint32_t h2=f2t(pw[gid*12+tg+4]);
        uint32_t h3=f2t(pw[(gid+8)*12+tg+4]);
        #pragma unroll
        for(int nt=0;nt<16;nt++){
            uint32_t b0=f2t(Vp[tg*128+nt*8+gid]);
            uint32_t b1=f2t(Vp[(tg+4)*128+nt*8+gid]);
            mma8(accO[nt],h0,h1,h2,h3,b0,b1);
        }
    }
    __syncthreads();

    // merge across 8 warps (scratch aliased onto Ks, now dead)
    for(int j=tid;j<2144;j+=256) sm[j]=0.f;
    __syncthreads();
    if(tg==0){ msh[warp*16+gid]=m0; msh[warp*16+gid+8]=m1; }
    __syncthreads();
    float M0=-1e30f,M1=-1e30f;
    #pragma unroll
    for(int w=0;w<8;w++){ M0=fmaxf(M0,msh[w*16+gid]); M1=fmaxf(M1,msh[w*16+gid+8]); }
    float sc0=ex2(m0-M0), sc1=ex2(m1-M1);
    if(tg==0){ atomicAdd(&Lsum[gid],l0*sc0); atomicAdd(&Lsum[gid+8],l1*sc1); }
    #pragma unroll
    for(int nt=0;nt<16;nt++){
        atomicAdd(&Osum[gid*132+nt*8+2*tg],       accO[nt][0]*sc0);
        atomicAdd(&Osum[gid*132+nt*8+2*tg+1],     accO[nt][1]*sc0);
        atomicAdd(&Osum[(gid+8)*132+nt*8+2*tg],   accO[nt][2]*sc1);
        atomicAdd(&Osum[(gid+8)*132+nt*8+2*tg+1], accO[nt][3]*sc1);
    }
    __syncthreads();
    int b=bh>>4, h=bh&15;
    for(int j=tid;j<2048;j+=256){
        int s_=j>>7, d=j&127;
        g_ao[(b*16+s_)*2048 + h*128 + d] = Osum[s_*132+d]/Lsum[s_];
    }
}

extern "C" void kernel_launch(void* const* d_in, const int* in_sizes, int n_in,
                              void* d_out, int out_size)
{
    const float* x =(const float*)d_in[0];
    const float* kc=(const float*)d_in[1];
    const float* vc=(const float*)d_in[2];
    const float* Wq=(const float*)d_in[3]; const float* bq=(const float*)d_in[4];
    const float* Wk=(const float*)d_in[5]; const float* bk=(const float*)d_in[6];
    const float* Wv=(const float*)d_in[7]; const float* bv=(const float*)d_in[8];
    const float* Wo=(const float*)d_in[9]; const float* bo=(const float*)d_in[10];
    cudaFuncSetAttribute(gemm_k<0>, cudaFuncAttributeMaxDynamicSharedMemorySize, GEMM_SMEM);
    cudaFuncSetAttribute(gemm_k<1>, cudaFuncAttributeMaxDynamicSharedMemorySize, GEMM_SMEM);
    cudaFuncSetAttribute(attn_k,    cudaFuncAttributeMaxDynamicSharedMemorySize, ATTN_SMEM);
    gemm_k<0><<<dim3(32,3,3),512,GEMM_SMEM>>>(x,Wq,Wk,Wv);
    reduce_qkv<<<384,512>>>(bq,bk,bv);
    attn_k<<<128,256,ATTN_SMEM>>>(kc,vc);
    gemm_k<1><<<dim3(32,8),512,GEMM_SMEM>>>(nullptr,Wo,Wo,Wo);
    reduce_k<<<128,512>>>(bo,(float*)d_out);
}